// round 1
// baseline (speedup 1.0000x reference)
#include <cuda_runtime.h>
#include <math.h>

// Problem constants
#define BB   2
#define SS   2048
#define DD   4096
#define HH   32
#define KVH  8
#define HD   128
#define SWW  4096
#define MM   (BB*SS)          // 4096 rows
#define NEGV (-1.0e9f)
#define SCALE (0.08838834764831845f)  // 128^-0.5

// ---------------- scratch (module-static, no runtime alloc) ----------------
__device__ float g_q[(size_t)MM * (HH*HD)];      // 4096 x 4096
__device__ float g_k[(size_t)MM * (KVH*HD)];     // 4096 x 1024
__device__ float g_v[(size_t)MM * (KVH*HD)];     // 4096 x 1024
__device__ float g_attn[(size_t)MM * (HH*HD)];   // 4096 x 4096

// ---------------- SGEMM: C[M,N] = A[M,K] @ B[K,N], fp32, 128x128x8 ----------
__global__ void __launch_bounds__(256) sgemm_kernel(
    const float* __restrict__ A, const float* __restrict__ B,
    float* __restrict__ C, int M, int N, int K)
{
    const int BM = 128, BN = 128, BK = 8;
    __shared__ float As[BK][BM];   // transposed A tile
    __shared__ float Bs[BK][BN];

    int tid = threadIdx.x;
    int tx = tid & 15;         // 0..15 -> 8 cols each
    int ty = tid >> 4;         // 0..15 -> 8 rows each

    int brow = blockIdx.y, bcol = blockIdx.x;

    // A tile load mapping: 128 rows x 8 cols = 256 float4
    int aRow = tid >> 1;            // 0..127
    int aCol = (tid & 1) * 4;       // 0 or 4
    // B tile load mapping: 8 rows x 128 cols = 256 float4
    int bRow = tid >> 5;            // 0..7
    int bCol = (tid & 31) * 4;      // 0..124

    const float* Ap = A + (size_t)brow * BM * K;
    const float* Bp = B + bcol * BN;

    float acc[8][8];
#pragma unroll
    for (int i = 0; i < 8; i++)
#pragma unroll
        for (int j = 0; j < 8; j++) acc[i][j] = 0.f;

    for (int k0 = 0; k0 < K; k0 += BK) {
        float4 a4 = *(const float4*)(Ap + (size_t)aRow * K + k0 + aCol);
        As[aCol + 0][aRow] = a4.x;
        As[aCol + 1][aRow] = a4.y;
        As[aCol + 2][aRow] = a4.z;
        As[aCol + 3][aRow] = a4.w;
        float4 b4 = *(const float4*)(Bp + (size_t)(k0 + bRow) * N + bCol);
        *(float4*)&Bs[bRow][bCol] = b4;
        __syncthreads();

#pragma unroll
        for (int kk = 0; kk < BK; kk++) {
            float ra[8], rb[8];
            float4 a0 = *(const float4*)&As[kk][ty * 8];
            float4 a1 = *(const float4*)&As[kk][ty * 8 + 4];
            ra[0]=a0.x; ra[1]=a0.y; ra[2]=a0.z; ra[3]=a0.w;
            ra[4]=a1.x; ra[5]=a1.y; ra[6]=a1.z; ra[7]=a1.w;
            float4 b0 = *(const float4*)&Bs[kk][tx * 8];
            float4 b1 = *(const float4*)&Bs[kk][tx * 8 + 4];
            rb[0]=b0.x; rb[1]=b0.y; rb[2]=b0.z; rb[3]=b0.w;
            rb[4]=b1.x; rb[5]=b1.y; rb[6]=b1.z; rb[7]=b1.w;
#pragma unroll
            for (int i = 0; i < 8; i++)
#pragma unroll
                for (int j = 0; j < 8; j++)
                    acc[i][j] = fmaf(ra[i], rb[j], acc[i][j]);
        }
        __syncthreads();
    }

#pragma unroll
    for (int i = 0; i < 8; i++) {
        float* crow = C + (size_t)(brow * BM + ty * 8 + i) * N + bcol * BN + tx * 8;
        float4 c0 = make_float4(acc[i][0], acc[i][1], acc[i][2], acc[i][3]);
        float4 c1 = make_float4(acc[i][4], acc[i][5], acc[i][6], acc[i][7]);
        *(float4*)(crow)     = c0;
        *(float4*)(crow + 4) = c1;
    }
}

// ---------------- RoPE (in place) ----------------
// buf: [MM, heads*HD] row-major; pair (2i, 2i+1) within each head rotated by
// cos/sin[s, i], s = row % SS.
__global__ void rope_kernel(float* __restrict__ buf,
                            const float* __restrict__ cosf,
                            const float* __restrict__ sinf,
                            int heads)
{
    int idx = blockIdx.x * blockDim.x + threadIdx.x;
    int total = MM * heads * (HD / 2);
    if (idx >= total) return;
    int i   = idx & 63;            // 0..63
    int t   = idx >> 6;
    int h   = t % heads;
    int row = t / heads;
    int s   = row & (SS - 1);
    float c  = cosf[s * 64 + i];
    float sn = sinf[s * 64 + i];
    float* p = buf + (size_t)row * heads * HD + h * HD + 2 * i;
    float x1 = p[0], x2 = p[1];
    p[0] = x1 * c - x2 * sn;
    p[1] = x1 * sn + x2 * c;
}

// ---------------- cache write-back ----------------
// out_cache[b,t,kv,hd]: for t < SS -> where(x != 0, x, cache_in), else cache_in.
__global__ void cache_kernel(const float* __restrict__ kbuf,
                             const float* __restrict__ vbuf,
                             const float* __restrict__ ck_in,
                             const float* __restrict__ cv_in,
                             float* __restrict__ out_ck,
                             float* __restrict__ out_cv)
{
    int idx = blockIdx.x * blockDim.x + threadIdx.x;
    const int total = BB * SWW * KVH * HD;   // 8,388,608
    if (idx >= total) return;
    int d = idx & 1023;                 // kv*HD + hd
    int t = (idx >> 10) & (SWW - 1);
    int b = idx >> 22;                  // idx / (SWW*1024)
    float ck = ck_in[idx];
    float cv = cv_in[idx];
    if (t < SS) {
        float xk = kbuf[(size_t)(b * SS + t) * (KVH * HD) + d];
        float xv = vbuf[(size_t)(b * SS + t) * (KVH * HD) + d];
        ck = (xk != 0.f) ? xk : ck;
        cv = (xv != 0.f) ? xv : cv;
    }
    out_ck[idx] = ck;
    out_cv[idx] = cv;
}

// ---------------- flash attention (causal, fp32) ----------------
// grid: (S/64, H, B), block 256. Group of 4 lanes owns one q row (32 dims each).
// One 32KB smem buffer reused for K then V per tile, XOR-swizzled float4s.
__global__ void __launch_bounds__(256) flash_kernel(
    const float* __restrict__ q, const float* __restrict__ k,
    const float* __restrict__ v, float* __restrict__ o_out)
{
    __shared__ float4 kv[64 * 32];   // 64 rows x 128 floats

    int qb = blockIdx.x, h = blockIdx.y, b = blockIdx.z;
    int tid = threadIdx.x;
    int g = tid >> 2;        // 0..63: q row within block
    int lane4 = tid & 3;     // 0..3 : 32-dim segment
    int r = qb * 64 + g;     // global q row
    int kvh = h >> 2;        // GQA: repeat(.,4) -> kv head = h/4

    float qreg[32];
    {
        const float* qrow = q + (size_t)(b * SS + r) * (HH * HD) + h * HD + lane4 * 32;
#pragma unroll
        for (int j4 = 0; j4 < 8; j4++) {
            float4 t = *(const float4*)(qrow + 4 * j4);
            qreg[4*j4+0] = t.x * SCALE; qreg[4*j4+1] = t.y * SCALE;
            qreg[4*j4+2] = t.z * SCALE; qreg[4*j4+3] = t.w * SCALE;
        }
    }

    float o[32];
#pragma unroll
    for (int j = 0; j < 32; j++) o[j] = 0.f;
    float m = -INFINITY, l = 0.f;

    const int ntiles = qb + 1;
    for (int t = 0; t < ntiles; t++) {
        int kc0 = t * 64;
        __syncthreads();   // previous V reads finished
        // ---- load K tile (swizzled) ----
        {
            const float* kb = k + (size_t)(b * SS + kc0) * (KVH * HD) + kvh * HD;
            for (int f = tid; f < 2048; f += 256) {
                int row = f >> 5, c4 = f & 31;
                float4 val = *(const float4*)(kb + (size_t)row * (KVH * HD) + c4 * 4);
                kv[row * 32 + (c4 ^ (c4 >> 3))] = val;
            }
        }
        __syncthreads();

        // ---- scores ----
        float p[16];
        float tmax = -INFINITY;
#pragma unroll
        for (int c = 0; c < 64; c++) {
            float acc = 0.f;
            const float4* kr = kv + c * 32;
#pragma unroll
            for (int ii = 0; ii < 8; ii++) {
                int d4 = lane4 * 8 + ii;
                float4 kk = kr[d4 ^ (d4 >> 3)];
                acc = fmaf(qreg[ii*4+0], kk.x, acc);
                acc = fmaf(qreg[ii*4+1], kk.y, acc);
                acc = fmaf(qreg[ii*4+2], kk.z, acc);
                acc = fmaf(qreg[ii*4+3], kk.w, acc);
            }
            acc += __shfl_xor_sync(0xffffffffu, acc, 1);
            acc += __shfl_xor_sync(0xffffffffu, acc, 2);
            if (kc0 + c > r) acc = NEGV;   // exp underflows to 0, same as ref
            tmax = fmaxf(tmax, acc);
            if ((c & 3) == lane4) p[c >> 2] = acc;
        }

        float m_new = fmaxf(m, tmax);
        float corr = __expf(m - m_new);
        float lsum = 0.f;
#pragma unroll
        for (int i = 0; i < 16; i++) {
            p[i] = __expf(p[i] - m_new);
            lsum += p[i];
        }
        lsum += __shfl_xor_sync(0xffffffffu, lsum, 1);
        lsum += __shfl_xor_sync(0xffffffffu, lsum, 2);
        l = l * corr + lsum;
        m = m_new;
#pragma unroll
        for (int j = 0; j < 32; j++) o[j] *= corr;

        __syncthreads();   // score reads of kv finished
        // ---- load V tile (swizzled) ----
        {
            const float* vb = v + (size_t)(b * SS + kc0) * (KVH * HD) + kvh * HD;
            for (int f = tid; f < 2048; f += 256) {
                int row = f >> 5, c4 = f & 31;
                float4 val = *(const float4*)(vb + (size_t)row * (KVH * HD) + c4 * 4);
                kv[row * 32 + (c4 ^ (c4 >> 3))] = val;
            }
        }
        __syncthreads();

        // ---- o += P @ V ----
        int lane = tid & 31;
#pragma unroll
        for (int c = 0; c < 64; c++) {
            float pc = __shfl_sync(0xffffffffu, p[c >> 2], (lane & ~3) | (c & 3));
            const float4* vr = kv + c * 32;
#pragma unroll
            for (int ii = 0; ii < 8; ii++) {
                int d4 = lane4 * 8 + ii;
                float4 vv = vr[d4 ^ (d4 >> 3)];
                o[ii*4+0] = fmaf(pc, vv.x, o[ii*4+0]);
                o[ii*4+1] = fmaf(pc, vv.y, o[ii*4+1]);
                o[ii*4+2] = fmaf(pc, vv.z, o[ii*4+2]);
                o[ii*4+3] = fmaf(pc, vv.w, o[ii*4+3]);
            }
        }
    }

    float inv = 1.f / l;
    float* orow = o_out + (size_t)(b * SS + r) * (HH * HD) + h * HD + lane4 * 32;
#pragma unroll
    for (int j4 = 0; j4 < 8; j4++) {
        float4 t = make_float4(o[4*j4+0]*inv, o[4*j4+1]*inv, o[4*j4+2]*inv, o[4*j4+3]*inv);
        *(float4*)(orow + 4 * j4) = t;
    }
}

// ---------------- launch ----------------
extern "C" void kernel_launch(void* const* d_in, const int* in_sizes, int n_in,
                              void* d_out, int out_size)
{
    const float* x    = (const float*)d_in[0];
    const float* cosf = (const float*)d_in[1];
    const float* sinf = (const float*)d_in[2];
    // d_in[3] = positions (arange(S)), d_in[4] = mask (causal NEG) -- folded in
    const float* ck_in = (const float*)d_in[5];
    const float* cv_in = (const float*)d_in[6];
    const float* wq   = (const float*)d_in[7];
    const float* wk   = (const float*)d_in[8];
    const float* wv   = (const float*)d_in[9];
    const float* wo   = (const float*)d_in[10];

    float* out   = (float*)d_out;                          // [MM, HH*HD]
    float* outck = out + (size_t)MM * (HH * HD);           // [BB,SWW,KVH,HD]
    float* outcv = outck + (size_t)BB * SWW * KVH * HD;

    float* q = nullptr; cudaGetSymbolAddress((void**)&q, g_q);
    float* k = nullptr; cudaGetSymbolAddress((void**)&k, g_k);
    float* v = nullptr; cudaGetSymbolAddress((void**)&v, g_v);
    float* a = nullptr; cudaGetSymbolAddress((void**)&a, g_attn);

    // QKV projections
    sgemm_kernel<<<dim3((HH*HD)/128,  MM/128), 256>>>(x, wq, q, MM, HH*HD, DD);
    sgemm_kernel<<<dim3((KVH*HD)/128, MM/128), 256>>>(x, wk, k, MM, KVH*HD, DD);
    sgemm_kernel<<<dim3((KVH*HD)/128, MM/128), 256>>>(x, wv, v, MM, KVH*HD, DD);

    // RoPE
    {
        int tq = MM * HH * 64;
        rope_kernel<<<(tq + 255) / 256, 256>>>(q, cosf, sinf, HH);
        int tk = MM * KVH * 64;
        rope_kernel<<<(tk + 255) / 256, 256>>>(k, cosf, sinf, KVH);
    }

    // KV cache write-back (k is RoPE'd, v raw)
    {
        int total = BB * SWW * KVH * HD;
        cache_kernel<<<(total + 255) / 256, 256>>>(k, v, ck_in, cv_in, outck, outcv);
    }

    // causal flash attention
    flash_kernel<<<dim3(SS / 64, HH, BB), 256>>>(q, k, v, a);

    // output projection
    sgemm_kernel<<<dim3((HH*HD)/128, MM/128), 256>>>(a, wo, out, MM, HH*HD, DD);
}

// round 2
// speedup vs baseline: 1.7618x; 1.7618x over previous
#include <cuda_runtime.h>
#include <math.h>
#include <stdint.h>

// Problem constants
#define BB   2
#define SS   2048
#define DD   4096
#define HH   32
#define KVH  8
#define HD   128
#define SWW  4096
#define MM   (BB*SS)          // 4096 rows
#define NEGV (-1.0e9f)
#define SCALE (0.08838834764831845f)  // 128^-0.5

// ---------------- scratch (module-static, no runtime alloc) ----------------
__device__ float g_q[(size_t)MM * (HH*HD)];      // 4096 x 4096
__device__ float g_k[(size_t)MM * (KVH*HD)];     // 4096 x 1024
__device__ float g_v[(size_t)MM * (KVH*HD)];     // 4096 x 1024
__device__ float g_attn[(size_t)MM * (HH*HD)];   // 4096 x 4096

// ---------------- TF32 tensor-core GEMM ----------------
// C[M,N] = A[M,K] @ B[K,N], row-major, fp32 in/out, TF32 MMA accumulate fp32.
// Block tile 128x128x32, 8 warps, warp tile 32x64 (2 m-frags x 8 n-frags of m16n8k8).
__device__ __forceinline__ uint32_t f2tf32(float f) {
    uint32_t r;
    asm("cvt.rna.tf32.f32 %0, %1;" : "=r"(r) : "f"(f));
    return r;
}

__global__ void __launch_bounds__(256) gemm_tf32_kernel(
    const float* __restrict__ A, const float* __restrict__ B,
    float* __restrict__ C, int M, int N, int K)
{
    __shared__ uint32_t As[128 * 36];   // stride 36: banks (4*row+col)%32 distinct
    __shared__ uint32_t Bs[32 * 136];   // stride 136: banks (8*k+col)%32 distinct

    const int tid  = threadIdx.x;
    const int warp = tid >> 5;
    const int lane = tid & 31;
    const int grp  = lane >> 2;    // 0..7
    const int tig  = lane & 3;     // 0..3
    const int warp_m = warp & 3;   // 4 m-slots of 32 rows
    const int warp_n = warp >> 2;  // 2 n-slots of 64 cols

    const int brow = blockIdx.y, bcol = blockIdx.x;

    float acc[2][8][4];
#pragma unroll
    for (int mt = 0; mt < 2; mt++)
#pragma unroll
        for (int nt = 0; nt < 8; nt++)
#pragma unroll
            for (int i = 0; i < 4; i++) acc[mt][nt][i] = 0.f;

    const float* Ap = A + (size_t)brow * 128 * K;
    const float* Bp = B + bcol * 128;

    for (int k0 = 0; k0 < K; k0 += 32) {
        // ---- global -> smem (with tf32 rounding) ----
#pragma unroll
        for (int i = 0; i < 4; i++) {
            int idx = tid + i * 256;
            int ar = idx >> 3, ac = (idx & 7) * 4;
            float4 a4 = *(const float4*)(Ap + (size_t)ar * K + k0 + ac);
            uint4 at;
            at.x = f2tf32(a4.x); at.y = f2tf32(a4.y);
            at.z = f2tf32(a4.z); at.w = f2tf32(a4.w);
            *(uint4*)&As[ar * 36 + ac] = at;

            int br = idx >> 5, bc = (idx & 31) * 4;
            float4 b4 = *(const float4*)(Bp + (size_t)(k0 + br) * N + bc);
            uint4 bt;
            bt.x = f2tf32(b4.x); bt.y = f2tf32(b4.y);
            bt.z = f2tf32(b4.z); bt.w = f2tf32(b4.w);
            *(uint4*)&Bs[br * 136 + bc] = bt;
        }
        __syncthreads();

        // ---- 4 k-steps of m16n8k8 ----
#pragma unroll
        for (int ks = 0; ks < 4; ks++) {
            int kb = ks * 8;
            uint32_t af[2][4], bf[8][2];
#pragma unroll
            for (int mt = 0; mt < 2; mt++) {
                int row0 = warp_m * 32 + mt * 16 + grp;
                af[mt][0] = As[row0 * 36 + kb + tig];
                af[mt][1] = As[(row0 + 8) * 36 + kb + tig];
                af[mt][2] = As[row0 * 36 + kb + 4 + tig];
                af[mt][3] = As[(row0 + 8) * 36 + kb + 4 + tig];
            }
#pragma unroll
            for (int nt = 0; nt < 8; nt++) {
                int colw = warp_n * 64 + nt * 8 + grp;
                bf[nt][0] = Bs[(kb + tig) * 136 + colw];
                bf[nt][1] = Bs[(kb + 4 + tig) * 136 + colw];
            }
#pragma unroll
            for (int mt = 0; mt < 2; mt++)
#pragma unroll
                for (int nt = 0; nt < 8; nt++) {
                    asm volatile(
                        "mma.sync.aligned.m16n8k8.row.col.f32.tf32.tf32.f32 "
                        "{%0,%1,%2,%3}, {%4,%5,%6,%7}, {%8,%9}, {%0,%1,%2,%3};"
                        : "+f"(acc[mt][nt][0]), "+f"(acc[mt][nt][1]),
                          "+f"(acc[mt][nt][2]), "+f"(acc[mt][nt][3])
                        : "r"(af[mt][0]), "r"(af[mt][1]), "r"(af[mt][2]), "r"(af[mt][3]),
                          "r"(bf[nt][0]), "r"(bf[nt][1]));
                }
        }
        __syncthreads();
    }

    // ---- epilogue ----
#pragma unroll
    for (int mt = 0; mt < 2; mt++) {
        int row = brow * 128 + warp_m * 32 + mt * 16 + grp;
#pragma unroll
        for (int nt = 0; nt < 8; nt++) {
            int col = bcol * 128 + warp_n * 64 + nt * 8 + tig * 2;
            *(float2*)(C + (size_t)row * N + col) =
                make_float2(acc[mt][nt][0], acc[mt][nt][1]);
            *(float2*)(C + (size_t)(row + 8) * N + col) =
                make_float2(acc[mt][nt][2], acc[mt][nt][3]);
        }
    }
}

// ---------------- RoPE (in place) ----------------
__global__ void rope_kernel(float* __restrict__ buf,
                            const float* __restrict__ cosf,
                            const float* __restrict__ sinf,
                            int heads)
{
    int idx = blockIdx.x * blockDim.x + threadIdx.x;
    int total = MM * heads * (HD / 2);
    if (idx >= total) return;
    int i   = idx & 63;
    int t   = idx >> 6;
    int h   = t % heads;
    int row = t / heads;
    int s   = row & (SS - 1);
    float c  = cosf[s * 64 + i];
    float sn = sinf[s * 64 + i];
    float* p = buf + (size_t)row * heads * HD + h * HD + 2 * i;
    float x1 = p[0], x2 = p[1];
    p[0] = x1 * c - x2 * sn;
    p[1] = x1 * sn + x2 * c;
}

// ---------------- cache write-back ----------------
__global__ void cache_kernel(const float* __restrict__ kbuf,
                             const float* __restrict__ vbuf,
                             const float* __restrict__ ck_in,
                             const float* __restrict__ cv_in,
                             float* __restrict__ out_ck,
                             float* __restrict__ out_cv)
{
    int idx = blockIdx.x * blockDim.x + threadIdx.x;
    const int total = BB * SWW * KVH * HD;
    if (idx >= total) return;
    int d = idx & 1023;
    int t = (idx >> 10) & (SWW - 1);
    int b = idx >> 22;
    float ck = ck_in[idx];
    float cv = cv_in[idx];
    if (t < SS) {
        float xk = kbuf[(size_t)(b * SS + t) * (KVH * HD) + d];
        float xv = vbuf[(size_t)(b * SS + t) * (KVH * HD) + d];
        ck = (xk != 0.f) ? xk : ck;
        cv = (xv != 0.f) ? xv : cv;
    }
    out_ck[idx] = ck;
    out_cv[idx] = cv;
}

// ---------------- flash attention (causal, fp32) ----------------
__global__ void __launch_bounds__(256) flash_kernel(
    const float* __restrict__ q, const float* __restrict__ k,
    const float* __restrict__ v, float* __restrict__ o_out)
{
    __shared__ float4 kv[64 * 32];

    int qb = blockIdx.x, h = blockIdx.y, b = blockIdx.z;
    int tid = threadIdx.x;
    int g = tid >> 2;
    int lane4 = tid & 3;
    int r = qb * 64 + g;
    int kvh = h >> 2;

    float qreg[32];
    {
        const float* qrow = q + (size_t)(b * SS + r) * (HH * HD) + h * HD + lane4 * 32;
#pragma unroll
        for (int j4 = 0; j4 < 8; j4++) {
            float4 t = *(const float4*)(qrow + 4 * j4);
            qreg[4*j4+0] = t.x * SCALE; qreg[4*j4+1] = t.y * SCALE;
            qreg[4*j4+2] = t.z * SCALE; qreg[4*j4+3] = t.w * SCALE;
        }
    }

    float o[32];
#pragma unroll
    for (int j = 0; j < 32; j++) o[j] = 0.f;
    float m = -INFINITY, l = 0.f;

    const int ntiles = qb + 1;
    for (int t = 0; t < ntiles; t++) {
        int kc0 = t * 64;
        __syncthreads();
        {
            const float* kb = k + (size_t)(b * SS + kc0) * (KVH * HD) + kvh * HD;
            for (int f = tid; f < 2048; f += 256) {
                int row = f >> 5, c4 = f & 31;
                float4 val = *(const float4*)(kb + (size_t)row * (KVH * HD) + c4 * 4);
                kv[row * 32 + (c4 ^ (c4 >> 3))] = val;
            }
        }
        __syncthreads();

        float p[16];
        float tmax = -INFINITY;
#pragma unroll
        for (int c = 0; c < 64; c++) {
            float acc = 0.f;
            const float4* kr = kv + c * 32;
#pragma unroll
            for (int ii = 0; ii < 8; ii++) {
                int d4 = lane4 * 8 + ii;
                float4 kk = kr[d4 ^ (d4 >> 3)];
                acc = fmaf(qreg[ii*4+0], kk.x, acc);
                acc = fmaf(qreg[ii*4+1], kk.y, acc);
                acc = fmaf(qreg[ii*4+2], kk.z, acc);
                acc = fmaf(qreg[ii*4+3], kk.w, acc);
            }
            acc += __shfl_xor_sync(0xffffffffu, acc, 1);
            acc += __shfl_xor_sync(0xffffffffu, acc, 2);
            if (kc0 + c > r) acc = NEGV;
            tmax = fmaxf(tmax, acc);
            if ((c & 3) == lane4) p[c >> 2] = acc;
        }

        float m_new = fmaxf(m, tmax);
        float corr = __expf(m - m_new);
        float lsum = 0.f;
#pragma unroll
        for (int i = 0; i < 16; i++) {
            p[i] = __expf(p[i] - m_new);
            lsum += p[i];
        }
        lsum += __shfl_xor_sync(0xffffffffu, lsum, 1);
        lsum += __shfl_xor_sync(0xffffffffu, lsum, 2);
        l = l * corr + lsum;
        m = m_new;
#pragma unroll
        for (int j = 0; j < 32; j++) o[j] *= corr;

        __syncthreads();
        {
            const float* vb = v + (size_t)(b * SS + kc0) * (KVH * HD) + kvh * HD;
            for (int f = tid; f < 2048; f += 256) {
                int row = f >> 5, c4 = f & 31;
                float4 val = *(const float4*)(vb + (size_t)row * (KVH * HD) + c4 * 4);
                kv[row * 32 + (c4 ^ (c4 >> 3))] = val;
            }
        }
        __syncthreads();

        int lane = tid & 31;
#pragma unroll
        for (int c = 0; c < 64; c++) {
            float pc = __shfl_sync(0xffffffffu, p[c >> 2], (lane & ~3) | (c & 3));
            const float4* vr = kv + c * 32;
#pragma unroll
            for (int ii = 0; ii < 8; ii++) {
                int d4 = lane4 * 8 + ii;
                float4 vv = vr[d4 ^ (d4 >> 3)];
                o[ii*4+0] = fmaf(pc, vv.x, o[ii*4+0]);
                o[ii*4+1] = fmaf(pc, vv.y, o[ii*4+1]);
                o[ii*4+2] = fmaf(pc, vv.z, o[ii*4+2]);
                o[ii*4+3] = fmaf(pc, vv.w, o[ii*4+3]);
            }
        }
    }

    float inv = 1.f / l;
    float* orow = o_out + (size_t)(b * SS + r) * (HH * HD) + h * HD + lane4 * 32;
#pragma unroll
    for (int j4 = 0; j4 < 8; j4++) {
        float4 t = make_float4(o[4*j4+0]*inv, o[4*j4+1]*inv, o[4*j4+2]*inv, o[4*j4+3]*inv);
        *(float4*)(orow + 4 * j4) = t;
    }
}

// ---------------- launch ----------------
extern "C" void kernel_launch(void* const* d_in, const int* in_sizes, int n_in,
                              void* d_out, int out_size)
{
    const float* x    = (const float*)d_in[0];
    const float* cosf = (const float*)d_in[1];
    const float* sinf = (const float*)d_in[2];
    const float* ck_in = (const float*)d_in[5];
    const float* cv_in = (const float*)d_in[6];
    const float* wq   = (const float*)d_in[7];
    const float* wk   = (const float*)d_in[8];
    const float* wv   = (const float*)d_in[9];
    const float* wo   = (const float*)d_in[10];

    float* out   = (float*)d_out;
    float* outck = out + (size_t)MM * (HH * HD);
    float* outcv = outck + (size_t)BB * SWW * KVH * HD;

    float* q = nullptr; cudaGetSymbolAddress((void**)&q, g_q);
    float* k = nullptr; cudaGetSymbolAddress((void**)&k, g_k);
    float* v = nullptr; cudaGetSymbolAddress((void**)&v, g_v);
    float* a = nullptr; cudaGetSymbolAddress((void**)&a, g_attn);

    // QKV projections (TF32 tensor cores)
    gemm_tf32_kernel<<<dim3((HH*HD)/128,  MM/128), 256>>>(x, wq, q, MM, HH*HD, DD);
    gemm_tf32_kernel<<<dim3((KVH*HD)/128, MM/128), 256>>>(x, wk, k, MM, KVH*HD, DD);
    gemm_tf32_kernel<<<dim3((KVH*HD)/128, MM/128), 256>>>(x, wv, v, MM, KVH*HD, DD);

    // RoPE
    {
        int tq = MM * HH * 64;
        rope_kernel<<<(tq + 255) / 256, 256>>>(q, cosf, sinf, HH);
        int tk = MM * KVH * 64;
        rope_kernel<<<(tk + 255) / 256, 256>>>(k, cosf, sinf, KVH);
    }

    // KV cache write-back
    {
        int total = BB * SWW * KVH * HD;
        cache_kernel<<<(total + 255) / 256, 256>>>(k, v, ck_in, cv_in, outck, outcv);
    }

    // causal flash attention
    flash_kernel<<<dim3(SS / 64, HH, BB), 256>>>(q, k, v, a);

    // output projection
    gemm_tf32_kernel<<<dim3((HH*HD)/128, MM/128), 256>>>(a, wo, out, MM, HH*HD, DD);
}

// round 3
// speedup vs baseline: 2.6710x; 1.5161x over previous
#include <cuda_runtime.h>
#include <math.h>
#include <stdint.h>

// Problem constants
#define BB   2
#define SS   2048
#define DD   4096
#define HH   32
#define KVH  8
#define HD   128
#define SWW  4096
#define MM   (BB*SS)          // 4096 rows
#define NEGV (-1.0e9f)
#define SCALE (0.08838834764831845f)  // 128^-0.5

// ---------------- scratch (module-static, no runtime alloc) ----------------
__device__ float g_q[(size_t)MM * (HH*HD)];      // 4096 x 4096
__device__ float g_k[(size_t)MM * (KVH*HD)];     // 4096 x 1024
__device__ float g_v[(size_t)MM * (KVH*HD)];     // 4096 x 1024
__device__ float g_attn[(size_t)MM * (HH*HD)];   // 4096 x 4096

__device__ __forceinline__ uint32_t f2tf32(float f) {
    uint32_t r;
    asm("cvt.rna.tf32.f32 %0, %1;" : "=r"(r) : "f"(f));
    return r;
}

#define MMA_TF32(d, a0,a1,a2,a3, b0,b1) \
    asm volatile("mma.sync.aligned.m16n8k8.row.col.f32.tf32.tf32.f32 " \
        "{%0,%1,%2,%3}, {%4,%5,%6,%7}, {%8,%9}, {%0,%1,%2,%3};" \
        : "+f"(d[0]),"+f"(d[1]),"+f"(d[2]),"+f"(d[3]) \
        : "r"(a0),"r"(a1),"r"(a2),"r"(a3),"r"(b0),"r"(b1))

// ---------------- TF32 tensor-core GEMM (single pass) ----------------
// C[M,N] = A[M,K] @ B[K,N], row-major. Block 128x128x32, 8 warps.
__global__ void __launch_bounds__(256) gemm_tf32_kernel(
    const float* __restrict__ A, const float* __restrict__ B,
    float* __restrict__ C, int M, int N, int K)
{
    __shared__ uint32_t As[128 * 36];
    __shared__ uint32_t Bs[32 * 136];

    const int tid  = threadIdx.x;
    const int warp = tid >> 5;
    const int lane = tid & 31;
    const int grp  = lane >> 2;
    const int tig  = lane & 3;
    const int warp_m = warp & 3;
    const int warp_n = warp >> 2;

    const int brow = blockIdx.y, bcol = blockIdx.x;

    float acc[2][8][4];
#pragma unroll
    for (int mt = 0; mt < 2; mt++)
#pragma unroll
        for (int nt = 0; nt < 8; nt++)
#pragma unroll
            for (int i = 0; i < 4; i++) acc[mt][nt][i] = 0.f;

    const float* Ap = A + (size_t)brow * 128 * K;
    const float* Bp = B + bcol * 128;

    for (int k0 = 0; k0 < K; k0 += 32) {
#pragma unroll
        for (int i = 0; i < 4; i++) {
            int idx = tid + i * 256;
            int ar = idx >> 3, ac = (idx & 7) * 4;
            float4 a4 = *(const float4*)(Ap + (size_t)ar * K + k0 + ac);
            uint4 at;
            at.x = f2tf32(a4.x); at.y = f2tf32(a4.y);
            at.z = f2tf32(a4.z); at.w = f2tf32(a4.w);
            *(uint4*)&As[ar * 36 + ac] = at;

            int br = idx >> 5, bc = (idx & 31) * 4;
            float4 b4 = *(const float4*)(Bp + (size_t)(k0 + br) * N + bc);
            uint4 bt;
            bt.x = f2tf32(b4.x); bt.y = f2tf32(b4.y);
            bt.z = f2tf32(b4.z); bt.w = f2tf32(b4.w);
            *(uint4*)&Bs[br * 136 + bc] = bt;
        }
        __syncthreads();

#pragma unroll
        for (int ks = 0; ks < 4; ks++) {
            int kb = ks * 8;
            uint32_t af[2][4], bf[8][2];
#pragma unroll
            for (int mt = 0; mt < 2; mt++) {
                int row0 = warp_m * 32 + mt * 16 + grp;
                af[mt][0] = As[row0 * 36 + kb + tig];
                af[mt][1] = As[(row0 + 8) * 36 + kb + tig];
                af[mt][2] = As[row0 * 36 + kb + 4 + tig];
                af[mt][3] = As[(row0 + 8) * 36 + kb + 4 + tig];
            }
#pragma unroll
            for (int nt = 0; nt < 8; nt++) {
                int colw = warp_n * 64 + nt * 8 + grp;
                bf[nt][0] = Bs[(kb + tig) * 136 + colw];
                bf[nt][1] = Bs[(kb + 4 + tig) * 136 + colw];
            }
#pragma unroll
            for (int mt = 0; mt < 2; mt++)
#pragma unroll
                for (int nt = 0; nt < 8; nt++)
                    MMA_TF32(acc[mt][nt], af[mt][0], af[mt][1], af[mt][2], af[mt][3],
                             bf[nt][0], bf[nt][1]);
        }
        __syncthreads();
    }

#pragma unroll
    for (int mt = 0; mt < 2; mt++) {
        int row = brow * 128 + warp_m * 32 + mt * 16 + grp;
#pragma unroll
        for (int nt = 0; nt < 8; nt++) {
            int col = bcol * 128 + warp_n * 64 + nt * 8 + tig * 2;
            *(float2*)(C + (size_t)row * N + col) =
                make_float2(acc[mt][nt][0], acc[mt][nt][1]);
            *(float2*)(C + (size_t)(row + 8) * N + col) =
                make_float2(acc[mt][nt][2], acc[mt][nt][3]);
        }
    }
}

// ---------------- split-TF32 (x3) GEMM: near-fp32 accuracy ----------------
__global__ void __launch_bounds__(256) gemm_tf32x3_kernel(
    const float* __restrict__ A, const float* __restrict__ B,
    float* __restrict__ C, int M, int N, int K)
{
    extern __shared__ uint32_t sm[];
    uint32_t* Ash = sm;                 // 128*36
    uint32_t* Asl = Ash + 128 * 36;
    uint32_t* Bsh = Asl + 128 * 36;     // 32*136
    uint32_t* Bsl = Bsh + 32 * 136;

    const int tid  = threadIdx.x;
    const int warp = tid >> 5;
    const int lane = tid & 31;
    const int grp  = lane >> 2;
    const int tig  = lane & 3;
    const int warp_m = warp & 3;
    const int warp_n = warp >> 2;

    const int brow = blockIdx.y, bcol = blockIdx.x;

    float acc[2][8][4];
#pragma unroll
    for (int mt = 0; mt < 2; mt++)
#pragma unroll
        for (int nt = 0; nt < 8; nt++)
#pragma unroll
            for (int i = 0; i < 4; i++) acc[mt][nt][i] = 0.f;

    const float* Ap = A + (size_t)brow * 128 * K;
    const float* Bp = B + bcol * 128;

    for (int k0 = 0; k0 < K; k0 += 32) {
#pragma unroll
        for (int i = 0; i < 4; i++) {
            int idx = tid + i * 256;
            int ar = idx >> 3, ac = (idx & 7) * 4;
            float4 a4 = *(const float4*)(Ap + (size_t)ar * K + k0 + ac);
            float av[4] = {a4.x, a4.y, a4.z, a4.w};
#pragma unroll
            for (int j = 0; j < 4; j++) {
                uint32_t hi = f2tf32(av[j]);
                Ash[ar * 36 + ac + j] = hi;
                Asl[ar * 36 + ac + j] = f2tf32(av[j] - __uint_as_float(hi));
            }
            int br = idx >> 5, bc = (idx & 31) * 4;
            float4 b4 = *(const float4*)(Bp + (size_t)(k0 + br) * N + bc);
            float bv[4] = {b4.x, b4.y, b4.z, b4.w};
#pragma unroll
            for (int j = 0; j < 4; j++) {
                uint32_t hi = f2tf32(bv[j]);
                Bsh[br * 136 + bc + j] = hi;
                Bsl[br * 136 + bc + j] = f2tf32(bv[j] - __uint_as_float(hi));
            }
        }
        __syncthreads();

#pragma unroll
        for (int ks = 0; ks < 4; ks++) {
            int kb = ks * 8;
            uint32_t ah[2][4], al[2][4], bh[8][2], bl[8][2];
#pragma unroll
            for (int mt = 0; mt < 2; mt++) {
                int row0 = warp_m * 32 + mt * 16 + grp;
                int o0 = row0 * 36 + kb + tig, o1 = (row0 + 8) * 36 + kb + tig;
                ah[mt][0] = Ash[o0]; ah[mt][1] = Ash[o1];
                ah[mt][2] = Ash[o0 + 4]; ah[mt][3] = Ash[o1 + 4];
                al[mt][0] = Asl[o0]; al[mt][1] = Asl[o1];
                al[mt][2] = Asl[o0 + 4]; al[mt][3] = Asl[o1 + 4];
            }
#pragma unroll
            for (int nt = 0; nt < 8; nt++) {
                int colw = warp_n * 64 + nt * 8 + grp;
                bh[nt][0] = Bsh[(kb + tig) * 136 + colw];
                bh[nt][1] = Bsh[(kb + 4 + tig) * 136 + colw];
                bl[nt][0] = Bsl[(kb + tig) * 136 + colw];
                bl[nt][1] = Bsl[(kb + 4 + tig) * 136 + colw];
            }
#pragma unroll
            for (int mt = 0; mt < 2; mt++)
#pragma unroll
                for (int nt = 0; nt < 8; nt++) {
                    MMA_TF32(acc[mt][nt], ah[mt][0], ah[mt][1], ah[mt][2], ah[mt][3],
                             bh[nt][0], bh[nt][1]);
                    MMA_TF32(acc[mt][nt], ah[mt][0], ah[mt][1], ah[mt][2], ah[mt][3],
                             bl[nt][0], bl[nt][1]);
                    MMA_TF32(acc[mt][nt], al[mt][0], al[mt][1], al[mt][2], al[mt][3],
                             bh[nt][0], bh[nt][1]);
                }
        }
        __syncthreads();
    }

#pragma unroll
    for (int mt = 0; mt < 2; mt++) {
        int row = brow * 128 + warp_m * 32 + mt * 16 + grp;
#pragma unroll
        for (int nt = 0; nt < 8; nt++) {
            int col = bcol * 128 + warp_n * 64 + nt * 8 + tig * 2;
            *(float2*)(C + (size_t)row * N + col) =
                make_float2(acc[mt][nt][0], acc[mt][nt][1]);
            *(float2*)(C + (size_t)(row + 8) * N + col) =
                make_float2(acc[mt][nt][2], acc[mt][nt][3]);
        }
    }
}

// ---------------- RoPE (in place) ----------------
__global__ void rope_kernel(float* __restrict__ buf,
                            const float* __restrict__ cosf,
                            const float* __restrict__ sinf,
                            int heads)
{
    int idx = blockIdx.x * blockDim.x + threadIdx.x;
    int total = MM * heads * (HD / 2);
    if (idx >= total) return;
    int i   = idx & 63;
    int t   = idx >> 6;
    int h   = t % heads;
    int row = t / heads;
    int s   = row & (SS - 1);
    float c  = cosf[s * 64 + i];
    float sn = sinf[s * 64 + i];
    float* p = buf + (size_t)row * heads * HD + h * HD + 2 * i;
    float x1 = p[0], x2 = p[1];
    p[0] = x1 * c - x2 * sn;
    p[1] = x1 * sn + x2 * c;
}

// ---------------- cache write-back ----------------
__global__ void cache_kernel(const float* __restrict__ kbuf,
                             const float* __restrict__ vbuf,
                             const float* __restrict__ ck_in,
                             const float* __restrict__ cv_in,
                             float* __restrict__ out_ck,
                             float* __restrict__ out_cv)
{
    int idx = blockIdx.x * blockDim.x + threadIdx.x;
    const int total = BB * SWW * KVH * HD;
    if (idx >= total) return;
    int d = idx & 1023;
    int t = (idx >> 10) & (SWW - 1);
    int b = idx >> 22;
    float ck = ck_in[idx];
    float cv = cv_in[idx];
    if (t < SS) {
        float xk = kbuf[(size_t)(b * SS + t) * (KVH * HD) + d];
        float xv = vbuf[(size_t)(b * SS + t) * (KVH * HD) + d];
        ck = (xk != 0.f) ? xk : ck;
        cv = (xv != 0.f) ? xv : cv;
    }
    out_ck[idx] = ck;
    out_cv[idx] = cv;
}

// ---------------- tensor-core flash attention (causal) ----------------
// Br=128 q rows per block (8 warps x 16 rows), Bc=32 kv cols per tile.
// QK^T: split-tf32 (3 MMAs) for ~fp32 score accuracy. PV: single tf32.
// smem (u32): Qh[128][132], Ql[128][132], Kh[32][132], Kl[32][132],
//             Vt[128][33] (transposed V), Ps[128][36]  => 204288 bytes
#define FL_SMEM_BYTES 204288

__global__ void __launch_bounds__(256, 1) flash_tc_kernel(
    const float* __restrict__ q, const float* __restrict__ k,
    const float* __restrict__ v, float* __restrict__ o_out)
{
    extern __shared__ uint32_t sh[];
    uint32_t* Qh = sh;                    // 128*132
    uint32_t* Ql = Qh + 128 * 132;
    uint32_t* Kh = Ql + 128 * 132;        // 32*132
    uint32_t* Kl = Kh + 32 * 132;
    uint32_t* Vt = Kl + 32 * 132;         // 128*33  Vt[d][c]
    uint32_t* Ps = Vt + 128 * 33;         // 128*36

    const int qb  = gridDim.x - 1 - blockIdx.x;   // heavy blocks first
    const int h   = blockIdx.y, b = blockIdx.z;
    const int kvh = h >> 2;
    const int tid = threadIdx.x, warp = tid >> 5, lane = tid & 31;
    const int grp = lane >> 2, tig = lane & 3;
    const int w16 = warp * 16;
    const int rbase = qb * 128;

    // ---- load Q tile (scaled, split hi/lo) ----
    {
        const float* qg = q + ((size_t)(b * SS) + rbase) * (HH * HD) + h * HD;
#pragma unroll
        for (int i = 0; i < 16; i++) {
            int f = tid + i * 256;
            int r = f >> 5, c4 = (f & 31) * 4;
            float4 t4 = *(const float4*)(qg + (size_t)r * (HH * HD) + c4);
            float va[4] = {t4.x * SCALE, t4.y * SCALE, t4.z * SCALE, t4.w * SCALE};
#pragma unroll
            for (int j = 0; j < 4; j++) {
                uint32_t hi = f2tf32(va[j]);
                Qh[r * 132 + c4 + j] = hi;
                Ql[r * 132 + c4 + j] = f2tf32(va[j] - __uint_as_float(hi));
            }
        }
    }

    float O[16][4];
#pragma unroll
    for (int nf = 0; nf < 16; nf++)
#pragma unroll
        for (int i = 0; i < 4; i++) O[nf][i] = 0.f;
    float m0 = -INFINITY, m1 = -INFINITY, l0 = 0.f, l1 = 0.f;

    const int ntiles = (qb + 1) * 4;
    for (int t = 0; t < ntiles; t++) {
        int tc0 = t * 32;
        __syncthreads();
        // ---- load K tile (split hi/lo) ----
        {
            const float* kg = k + ((size_t)(b * SS) + tc0) * (KVH * HD) + kvh * HD;
#pragma unroll
            for (int i = 0; i < 4; i++) {
                int f = tid + i * 256;
                int r = f >> 5, c4 = (f & 31) * 4;
                float4 t4 = *(const float4*)(kg + (size_t)r * (KVH * HD) + c4);
                float va[4] = {t4.x, t4.y, t4.z, t4.w};
#pragma unroll
                for (int j = 0; j < 4; j++) {
                    uint32_t hi = f2tf32(va[j]);
                    Kh[r * 132 + c4 + j] = hi;
                    Kl[r * 132 + c4 + j] = f2tf32(va[j] - __uint_as_float(hi));
                }
            }
        }
        // ---- load V tile transposed: Vt[d][c] ----
        {
            const float* vg = v + ((size_t)(b * SS) + tc0) * (KVH * HD) + kvh * HD;
#pragma unroll
            for (int i = 0; i < 4; i++) {
                int f = tid + i * 256;
                int c = f >> 5, j4 = (f & 31) * 4;
                float4 t4 = *(const float4*)(vg + (size_t)c * (KVH * HD) + j4);
                Vt[(j4 + 0) * 33 + c] = f2tf32(t4.x);
                Vt[(j4 + 1) * 33 + c] = f2tf32(t4.y);
                Vt[(j4 + 2) * 33 + c] = f2tf32(t4.z);
                Vt[(j4 + 3) * 33 + c] = f2tf32(t4.w);
            }
        }
        __syncthreads();

        // ---- S = Q @ K^T (split-tf32, 3 MMAs) ----
        float sacc[4][4];
#pragma unroll
        for (int nf = 0; nf < 4; nf++)
#pragma unroll
            for (int i = 0; i < 4; i++) sacc[nf][i] = 0.f;

#pragma unroll
        for (int ks = 0; ks < 16; ks++) {
            int kb = ks * 8;
            int ra0 = (w16 + grp) * 132 + kb + tig;
            int ra1 = (w16 + grp + 8) * 132 + kb + tig;
            uint32_t ah0 = Qh[ra0], ah1 = Qh[ra1], ah2 = Qh[ra0 + 4], ah3 = Qh[ra1 + 4];
            uint32_t al0 = Ql[ra0], al1 = Ql[ra1], al2 = Ql[ra0 + 4], al3 = Ql[ra1 + 4];
#pragma unroll
            for (int nf = 0; nf < 4; nf++) {
                int rb = (nf * 8 + grp) * 132 + kb + tig;
                uint32_t bh0 = Kh[rb], bh1 = Kh[rb + 4];
                uint32_t bl0 = Kl[rb], bl1 = Kl[rb + 4];
                MMA_TF32(sacc[nf], ah0, ah1, ah2, ah3, bh0, bh1);
                MMA_TF32(sacc[nf], ah0, ah1, ah2, ah3, bl0, bl1);
                MMA_TF32(sacc[nf], al0, al1, al2, al3, bh0, bh1);
            }
        }

        // ---- causal mask ----
        if (t >= 4 * qb) {
            int row0 = rbase + w16 + grp, row1 = row0 + 8;
#pragma unroll
            for (int nf = 0; nf < 4; nf++) {
                int col = tc0 + nf * 8 + 2 * tig;
                if (col     > row0) sacc[nf][0] = NEGV;
                if (col + 1 > row0) sacc[nf][1] = NEGV;
                if (col     > row1) sacc[nf][2] = NEGV;
                if (col + 1 > row1) sacc[nf][3] = NEGV;
            }
        }

        // ---- online softmax ----
        float mx0 = -INFINITY, mx1 = -INFINITY;
#pragma unroll
        for (int nf = 0; nf < 4; nf++) {
            mx0 = fmaxf(mx0, fmaxf(sacc[nf][0], sacc[nf][1]));
            mx1 = fmaxf(mx1, fmaxf(sacc[nf][2], sacc[nf][3]));
        }
        mx0 = fmaxf(mx0, __shfl_xor_sync(0xffffffffu, mx0, 1));
        mx0 = fmaxf(mx0, __shfl_xor_sync(0xffffffffu, mx0, 2));
        mx1 = fmaxf(mx1, __shfl_xor_sync(0xffffffffu, mx1, 1));
        mx1 = fmaxf(mx1, __shfl_xor_sync(0xffffffffu, mx1, 2));

        float nm0 = fmaxf(m0, mx0), nm1 = fmaxf(m1, mx1);
        float cr0 = __expf(m0 - nm0), cr1 = __expf(m1 - nm1);
        float s0 = 0.f, s1 = 0.f;
        int pr0 = (w16 + grp) * 36 + 2 * tig;
        int pr1 = (w16 + grp + 8) * 36 + 2 * tig;
#pragma unroll
        for (int nf = 0; nf < 4; nf++) {
            float p0 = __expf(sacc[nf][0] - nm0);
            float p1 = __expf(sacc[nf][1] - nm0);
            float p2 = __expf(sacc[nf][2] - nm1);
            float p3 = __expf(sacc[nf][3] - nm1);
            s0 += p0 + p1; s1 += p2 + p3;
            Ps[pr0 + nf * 8]     = f2tf32(p0);
            Ps[pr0 + nf * 8 + 1] = f2tf32(p1);
            Ps[pr1 + nf * 8]     = f2tf32(p2);
            Ps[pr1 + nf * 8 + 1] = f2tf32(p3);
        }
        s0 += __shfl_xor_sync(0xffffffffu, s0, 1);
        s0 += __shfl_xor_sync(0xffffffffu, s0, 2);
        s1 += __shfl_xor_sync(0xffffffffu, s1, 1);
        s1 += __shfl_xor_sync(0xffffffffu, s1, 2);
        l0 = l0 * cr0 + s0;
        l1 = l1 * cr1 + s1;
        m0 = nm0; m1 = nm1;
#pragma unroll
        for (int nf = 0; nf < 16; nf++) {
            O[nf][0] *= cr0; O[nf][1] *= cr0;
            O[nf][2] *= cr1; O[nf][3] *= cr1;
        }
        __syncwarp();

        // ---- O += P @ V ----
#pragma unroll
        for (int ks = 0; ks < 4; ks++) {
            int kb = ks * 8;
            int rp0 = (w16 + grp) * 36 + kb + tig;
            int rp1 = (w16 + grp + 8) * 36 + kb + tig;
            uint32_t pa0 = Ps[rp0], pa1 = Ps[rp1], pa2 = Ps[rp0 + 4], pa3 = Ps[rp1 + 4];
#pragma unroll
            for (int nf = 0; nf < 16; nf++) {
                int rv = (nf * 8 + grp) * 33 + kb + tig;
                uint32_t b0 = Vt[rv], b1 = Vt[rv + 4];
                MMA_TF32(O[nf], pa0, pa1, pa2, pa3, b0, b1);
            }
        }
        __syncwarp();
    }

    // ---- epilogue ----
    float inv0 = 1.f / l0, inv1 = 1.f / l1;
    float* og = o_out + ((size_t)(b * SS) + rbase + w16) * (HH * HD) + h * HD;
#pragma unroll
    for (int nf = 0; nf < 16; nf++) {
        int col = nf * 8 + 2 * tig;
        *(float2*)(og + (size_t)grp * (HH * HD) + col) =
            make_float2(O[nf][0] * inv0, O[nf][1] * inv0);
        *(float2*)(og + (size_t)(grp + 8) * (HH * HD) + col) =
            make_float2(O[nf][2] * inv1, O[nf][3] * inv1);
    }
}

// ---------------- launch ----------------
extern "C" void kernel_launch(void* const* d_in, const int* in_sizes, int n_in,
                              void* d_out, int out_size)
{
    const float* x    = (const float*)d_in[0];
    const float* cosf = (const float*)d_in[1];
    const float* sinf = (const float*)d_in[2];
    const float* ck_in = (const float*)d_in[5];
    const float* cv_in = (const float*)d_in[6];
    const float* wq   = (const float*)d_in[7];
    const float* wk   = (const float*)d_in[8];
    const float* wv   = (const float*)d_in[9];
    const float* wo   = (const float*)d_in[10];

    float* out   = (float*)d_out;
    float* outck = out + (size_t)MM * (HH * HD);
    float* outcv = outck + (size_t)BB * SWW * KVH * HD;

    float* q = nullptr; cudaGetSymbolAddress((void**)&q, g_q);
    float* k = nullptr; cudaGetSymbolAddress((void**)&k, g_k);
    float* v = nullptr; cudaGetSymbolAddress((void**)&v, g_v);
    float* a = nullptr; cudaGetSymbolAddress((void**)&a, g_attn);

    static bool attr_done = false;
    if (!attr_done) {
        cudaFuncSetAttribute(flash_tc_kernel,
                             cudaFuncAttributeMaxDynamicSharedMemorySize, FL_SMEM_BYTES);
        cudaFuncSetAttribute(gemm_tf32x3_kernel,
                             cudaFuncAttributeMaxDynamicSharedMemorySize, 71680);
        attr_done = true;
    }

    // Q projection (single-pass tf32)
    gemm_tf32_kernel<<<dim3((HH*HD)/128,  MM/128), 256>>>(x, wq, q, MM, HH*HD, DD);
    // K/V projections (split-tf32 x3: feeds cache outputs, needs ~fp32 accuracy)
    gemm_tf32x3_kernel<<<dim3((KVH*HD)/128, MM/128), 256, 71680>>>(x, wk, k, MM, KVH*HD, DD);
    gemm_tf32x3_kernel<<<dim3((KVH*HD)/128, MM/128), 256, 71680>>>(x, wv, v, MM, KVH*HD, DD);

    // RoPE
    {
        int tq = MM * HH * 64;
        rope_kernel<<<(tq + 255) / 256, 256>>>(q, cosf, sinf, HH);
        int tk = MM * KVH * 64;
        rope_kernel<<<(tk + 255) / 256, 256>>>(k, cosf, sinf, KVH);
    }

    // KV cache write-back
    {
        int total = BB * SWW * KVH * HD;
        cache_kernel<<<(total + 255) / 256, 256>>>(k, v, ck_in, cv_in, outck, outcv);
    }

    // tensor-core causal flash attention
    flash_tc_kernel<<<dim3(SS / 128, HH, BB), 256, FL_SMEM_BYTES>>>(q, k, v, a);

    // output projection (single-pass tf32)
    gemm_tf32_kernel<<<dim3((HH*HD)/128, MM/128), 256>>>(a, wo, out, MM, HH*HD, DD);
}

// round 4
// speedup vs baseline: 2.8750x; 1.0763x over previous
#include <cuda_runtime.h>
#include <math.h>
#include <stdint.h>

// Problem constants
#define BB   2
#define SS   2048
#define DD   4096
#define HH   32
#define KVH  8
#define HD   128
#define SWW  4096
#define MM   (BB*SS)          // 4096 rows
#define NEGV (-1.0e9f)
#define SCALE (0.08838834764831845f)  // 128^-0.5

// ---------------- scratch (module-static, no runtime alloc) ----------------
__device__ float g_q[(size_t)MM * (HH*HD)];      // 4096 x 4096
__device__ float g_k[(size_t)MM * (KVH*HD)];     // 4096 x 1024
__device__ float g_v[(size_t)MM * (KVH*HD)];     // 4096 x 1024
__device__ float g_attn[(size_t)MM * (HH*HD)];   // 4096 x 4096

__device__ __forceinline__ uint32_t f2tf32(float f) {
    uint32_t r;
    asm("cvt.rna.tf32.f32 %0, %1;" : "=r"(r) : "f"(f));
    return r;
}

#define MMA_TF32(d, a0,a1,a2,a3, b0,b1) \
    asm volatile("mma.sync.aligned.m16n8k8.row.col.f32.tf32.tf32.f32 " \
        "{%0,%1,%2,%3}, {%4,%5,%6,%7}, {%8,%9}, {%0,%1,%2,%3};" \
        : "+f"(d[0]),"+f"(d[1]),"+f"(d[2]),"+f"(d[3]) \
        : "r"(a0),"r"(a1),"r"(a2),"r"(a3),"r"(b0),"r"(b1))

// ================= TF32 GEMM, register-staged double buffering =============
// C[M,N] = A[M,K] @ B[K,N], row-major. Block 128x128x32, 8 warps.
// Buffer layout (u32): As[128*36], Bs[32*136] per stage; stage stride 8960.
#define G1_STAGE 8960
#define G1_SMEM  (2 * G1_STAGE * 4)

__global__ void __launch_bounds__(256) gemm_tf32_db_kernel(
    const float* __restrict__ A, const float* __restrict__ B,
    float* __restrict__ C, int M, int N, int K)
{
    extern __shared__ uint32_t sm[];

    const int tid  = threadIdx.x;
    const int warp = tid >> 5;
    const int lane = tid & 31;
    const int grp  = lane >> 2;
    const int tig  = lane & 3;
    const int warp_m = warp & 3;
    const int warp_n = warp >> 2;

    const int brow = blockIdx.y, bcol = blockIdx.x;

    // per-thread load coords
    const int ar = tid >> 3,  ac = (tid & 7) * 4;     // + i*32 rows
    const int br = tid >> 6,  bc = (tid & 63) * 2;    // B: 32x128 as float2 x2

    const float* Ap = A + (size_t)brow * 128 * K;
    const float* Bp = B + bcol * 128;

    float acc[2][8][4];
#pragma unroll
    for (int mt = 0; mt < 2; mt++)
#pragma unroll
        for (int nt = 0; nt < 8; nt++)
#pragma unroll
            for (int i = 0; i < 4; i++) acc[mt][nt][i] = 0.f;

    float4 ra[4]; float4 rb[4];
    // ---- prologue: load tile 0 ----
#pragma unroll
    for (int i = 0; i < 4; i++) {
        int idx = tid + i * 256;
        ra[i] = *(const float4*)(Ap + (size_t)(idx >> 3) * K + ((idx & 7) * 4));
        rb[i] = *(const float4*)(Bp + (size_t)(idx >> 5) * N + ((idx & 31) * 4));
    }
    {
        uint32_t* As = sm; uint32_t* Bs = sm + 128 * 36;
#pragma unroll
        for (int i = 0; i < 4; i++) {
            int idx = tid + i * 256;
            int r = idx >> 3, c = (idx & 7) * 4;
            uint4 t; t.x = f2tf32(ra[i].x); t.y = f2tf32(ra[i].y);
            t.z = f2tf32(ra[i].z); t.w = f2tf32(ra[i].w);
            *(uint4*)&As[r * 36 + c] = t;
            int r2 = idx >> 5, c2 = (idx & 31) * 4;
            uint4 u; u.x = f2tf32(rb[i].x); u.y = f2tf32(rb[i].y);
            u.z = f2tf32(rb[i].z); u.w = f2tf32(rb[i].w);
            *(uint4*)&Bs[r2 * 136 + c2] = u;
        }
    }
    __syncthreads();

    const int nk = K >> 5;
    for (int kt = 0; kt < nk; kt++) {
        // ---- issue next tile loads (LDGs in flight during MMA) ----
        if (kt + 1 < nk) {
            int k0 = (kt + 1) << 5;
#pragma unroll
            for (int i = 0; i < 4; i++) {
                int idx = tid + i * 256;
                ra[i] = *(const float4*)(Ap + (size_t)(idx >> 3) * K + k0 + ((idx & 7) * 4));
                rb[i] = *(const float4*)(Bp + (size_t)(k0 + (idx >> 5)) * N + ((idx & 31) * 4));
            }
        }
        // ---- compute on current buffer ----
        {
            uint32_t* As = sm + (kt & 1) * G1_STAGE;
            uint32_t* Bs = As + 128 * 36;
#pragma unroll
            for (int ks = 0; ks < 4; ks++) {
                int kb = ks * 8;
                uint32_t af[2][4], bf[8][2];
#pragma unroll
                for (int mt = 0; mt < 2; mt++) {
                    int row0 = warp_m * 32 + mt * 16 + grp;
                    af[mt][0] = As[row0 * 36 + kb + tig];
                    af[mt][1] = As[(row0 + 8) * 36 + kb + tig];
                    af[mt][2] = As[row0 * 36 + kb + 4 + tig];
                    af[mt][3] = As[(row0 + 8) * 36 + kb + 4 + tig];
                }
#pragma unroll
                for (int nt = 0; nt < 8; nt++) {
                    int colw = warp_n * 64 + nt * 8 + grp;
                    bf[nt][0] = Bs[(kb + tig) * 136 + colw];
                    bf[nt][1] = Bs[(kb + 4 + tig) * 136 + colw];
                }
#pragma unroll
                for (int mt = 0; mt < 2; mt++)
#pragma unroll
                    for (int nt = 0; nt < 8; nt++)
                        MMA_TF32(acc[mt][nt], af[mt][0], af[mt][1], af[mt][2], af[mt][3],
                                 bf[nt][0], bf[nt][1]);
            }
        }
        // ---- store next tile into alternate buffer ----
        if (kt + 1 < nk) {
            uint32_t* As = sm + ((kt + 1) & 1) * G1_STAGE;
            uint32_t* Bs = As + 128 * 36;
#pragma unroll
            for (int i = 0; i < 4; i++) {
                int idx = tid + i * 256;
                int r = idx >> 3, c = (idx & 7) * 4;
                uint4 t; t.x = f2tf32(ra[i].x); t.y = f2tf32(ra[i].y);
                t.z = f2tf32(ra[i].z); t.w = f2tf32(ra[i].w);
                *(uint4*)&As[r * 36 + c] = t;
                int r2 = idx >> 5, c2 = (idx & 31) * 4;
                uint4 u; u.x = f2tf32(rb[i].x); u.y = f2tf32(rb[i].y);
                u.z = f2tf32(rb[i].z); u.w = f2tf32(rb[i].w);
                *(uint4*)&Bs[r2 * 136 + c2] = u;
            }
        }
        __syncthreads();
    }

#pragma unroll
    for (int mt = 0; mt < 2; mt++) {
        int row = brow * 128 + warp_m * 32 + mt * 16 + grp;
#pragma unroll
        for (int nt = 0; nt < 8; nt++) {
            int col = bcol * 128 + warp_n * 64 + nt * 8 + tig * 2;
            *(float2*)(C + (size_t)row * N + col) =
                make_float2(acc[mt][nt][0], acc[mt][nt][1]);
            *(float2*)(C + (size_t)(row + 8) * N + col) =
                make_float2(acc[mt][nt][2], acc[mt][nt][3]);
        }
    }
}

// ============ split-TF32 (x3) GEMM, register-staged double buffering ========
// stage layout (u32): Ash[4608] Asl[4608] Bsh[4352] Bsl[4352]; stride 17920
#define G3_STAGE 17920
#define G3_SMEM  (2 * G3_STAGE * 4)

__global__ void __launch_bounds__(256) gemm_tf32x3_db_kernel(
    const float* __restrict__ A, const float* __restrict__ B,
    float* __restrict__ C, int M, int N, int K)
{
    extern __shared__ uint32_t sm[];

    const int tid  = threadIdx.x;
    const int warp = tid >> 5;
    const int lane = tid & 31;
    const int grp  = lane >> 2;
    const int tig  = lane & 3;
    const int warp_m = warp & 3;
    const int warp_n = warp >> 2;

    const int brow = blockIdx.y, bcol = blockIdx.x;

    const float* Ap = A + (size_t)brow * 128 * K;
    const float* Bp = B + bcol * 128;

    float acc[2][8][4];
#pragma unroll
    for (int mt = 0; mt < 2; mt++)
#pragma unroll
        for (int nt = 0; nt < 8; nt++)
#pragma unroll
            for (int i = 0; i < 4; i++) acc[mt][nt][i] = 0.f;

    float4 ra[4]; float4 rb[4];
#pragma unroll
    for (int i = 0; i < 4; i++) {
        int idx = tid + i * 256;
        ra[i] = *(const float4*)(Ap + (size_t)(idx >> 3) * K + ((idx & 7) * 4));
        rb[i] = *(const float4*)(Bp + (size_t)(idx >> 5) * N + ((idx & 31) * 4));
    }
    {
        uint32_t* Ash = sm; uint32_t* Asl = Ash + 4608;
        uint32_t* Bsh = Asl + 4608; uint32_t* Bsl = Bsh + 4352;
#pragma unroll
        for (int i = 0; i < 4; i++) {
            int idx = tid + i * 256;
            int r = idx >> 3, c = (idx & 7) * 4;
            float av[4] = {ra[i].x, ra[i].y, ra[i].z, ra[i].w};
#pragma unroll
            for (int j = 0; j < 4; j++) {
                uint32_t hi = f2tf32(av[j]);
                Ash[r * 36 + c + j] = hi;
                Asl[r * 36 + c + j] = f2tf32(av[j] - __uint_as_float(hi));
            }
            int r2 = idx >> 5, c2 = (idx & 31) * 4;
            float bv[4] = {rb[i].x, rb[i].y, rb[i].z, rb[i].w};
#pragma unroll
            for (int j = 0; j < 4; j++) {
                uint32_t hi = f2tf32(bv[j]);
                Bsh[r2 * 136 + c2 + j] = hi;
                Bsl[r2 * 136 + c2 + j] = f2tf32(bv[j] - __uint_as_float(hi));
            }
        }
    }
    __syncthreads();

    const int nk = K >> 5;
    for (int kt = 0; kt < nk; kt++) {
        if (kt + 1 < nk) {
            int k0 = (kt + 1) << 5;
#pragma unroll
            for (int i = 0; i < 4; i++) {
                int idx = tid + i * 256;
                ra[i] = *(const float4*)(Ap + (size_t)(idx >> 3) * K + k0 + ((idx & 7) * 4));
                rb[i] = *(const float4*)(Bp + (size_t)(k0 + (idx >> 5)) * N + ((idx & 31) * 4));
            }
        }
        {
            uint32_t* Ash = sm + (kt & 1) * G3_STAGE;
            uint32_t* Asl = Ash + 4608;
            uint32_t* Bsh = Asl + 4608;
            uint32_t* Bsl = Bsh + 4352;
#pragma unroll
            for (int ks = 0; ks < 4; ks++) {
                int kb = ks * 8;
                uint32_t ah[2][4], al[2][4], bh[8][2], bl[8][2];
#pragma unroll
                for (int mt = 0; mt < 2; mt++) {
                    int row0 = warp_m * 32 + mt * 16 + grp;
                    int o0 = row0 * 36 + kb + tig, o1 = (row0 + 8) * 36 + kb + tig;
                    ah[mt][0] = Ash[o0]; ah[mt][1] = Ash[o1];
                    ah[mt][2] = Ash[o0 + 4]; ah[mt][3] = Ash[o1 + 4];
                    al[mt][0] = Asl[o0]; al[mt][1] = Asl[o1];
                    al[mt][2] = Asl[o0 + 4]; al[mt][3] = Asl[o1 + 4];
                }
#pragma unroll
                for (int nt = 0; nt < 8; nt++) {
                    int colw = warp_n * 64 + nt * 8 + grp;
                    bh[nt][0] = Bsh[(kb + tig) * 136 + colw];
                    bh[nt][1] = Bsh[(kb + 4 + tig) * 136 + colw];
                    bl[nt][0] = Bsl[(kb + tig) * 136 + colw];
                    bl[nt][1] = Bsl[(kb + 4 + tig) * 136 + colw];
                }
#pragma unroll
                for (int mt = 0; mt < 2; mt++)
#pragma unroll
                    for (int nt = 0; nt < 8; nt++) {
                        MMA_TF32(acc[mt][nt], ah[mt][0], ah[mt][1], ah[mt][2], ah[mt][3],
                                 bh[nt][0], bh[nt][1]);
                        MMA_TF32(acc[mt][nt], ah[mt][0], ah[mt][1], ah[mt][2], ah[mt][3],
                                 bl[nt][0], bl[nt][1]);
                        MMA_TF32(acc[mt][nt], al[mt][0], al[mt][1], al[mt][2], al[mt][3],
                                 bh[nt][0], bh[nt][1]);
                    }
            }
        }
        if (kt + 1 < nk) {
            uint32_t* Ash = sm + ((kt + 1) & 1) * G3_STAGE;
            uint32_t* Asl = Ash + 4608;
            uint32_t* Bsh = Asl + 4608;
            uint32_t* Bsl = Bsh + 4352;
#pragma unroll
            for (int i = 0; i < 4; i++) {
                int idx = tid + i * 256;
                int r = idx >> 3, c = (idx & 7) * 4;
                float av[4] = {ra[i].x, ra[i].y, ra[i].z, ra[i].w};
#pragma unroll
                for (int j = 0; j < 4; j++) {
                    uint32_t hi = f2tf32(av[j]);
                    Ash[r * 36 + c + j] = hi;
                    Asl[r * 36 + c + j] = f2tf32(av[j] - __uint_as_float(hi));
                }
                int r2 = idx >> 5, c2 = (idx & 31) * 4;
                float bv[4] = {rb[i].x, rb[i].y, rb[i].z, rb[i].w};
#pragma unroll
                for (int j = 0; j < 4; j++) {
                    uint32_t hi = f2tf32(bv[j]);
                    Bsh[r2 * 136 + c2 + j] = hi;
                    Bsl[r2 * 136 + c2 + j] = f2tf32(bv[j] - __uint_as_float(hi));
                }
            }
        }
        __syncthreads();
    }

#pragma unroll
    for (int mt = 0; mt < 2; mt++) {
        int row = brow * 128 + warp_m * 32 + mt * 16 + grp;
#pragma unroll
        for (int nt = 0; nt < 8; nt++) {
            int col = bcol * 128 + warp_n * 64 + nt * 8 + tig * 2;
            *(float2*)(C + (size_t)row * N + col) =
                make_float2(acc[mt][nt][0], acc[mt][nt][1]);
            *(float2*)(C + (size_t)(row + 8) * N + col) =
                make_float2(acc[mt][nt][2], acc[mt][nt][3]);
        }
    }
}

// ---------------- RoPE (in place) ----------------
__global__ void rope_kernel(float* __restrict__ buf,
                            const float* __restrict__ cosf,
                            const float* __restrict__ sinf,
                            int heads)
{
    int idx = blockIdx.x * blockDim.x + threadIdx.x;
    int total = MM * heads * (HD / 2);
    if (idx >= total) return;
    int i   = idx & 63;
    int t   = idx >> 6;
    int h   = t % heads;
    int row = t / heads;
    int s   = row & (SS - 1);
    float c  = cosf[s * 64 + i];
    float sn = sinf[s * 64 + i];
    float* p = buf + (size_t)row * heads * HD + h * HD + 2 * i;
    float x1 = p[0], x2 = p[1];
    p[0] = x1 * c - x2 * sn;
    p[1] = x1 * sn + x2 * c;
}

// ---------------- cache write-back ----------------
__global__ void cache_kernel(const float* __restrict__ kbuf,
                             const float* __restrict__ vbuf,
                             const float* __restrict__ ck_in,
                             const float* __restrict__ cv_in,
                             float* __restrict__ out_ck,
                             float* __restrict__ out_cv)
{
    int idx = blockIdx.x * blockDim.x + threadIdx.x;
    const int total = BB * SWW * KVH * HD;
    if (idx >= total) return;
    int d = idx & 1023;
    int t = (idx >> 10) & (SWW - 1);
    int b = idx >> 22;
    float ck = ck_in[idx];
    float cv = cv_in[idx];
    if (t < SS) {
        float xk = kbuf[(size_t)(b * SS + t) * (KVH * HD) + d];
        float xv = vbuf[(size_t)(b * SS + t) * (KVH * HD) + d];
        ck = (xk != 0.f) ? xk : ck;
        cv = (xv != 0.f) ? xv : cv;
    }
    out_ck[idx] = ck;
    out_cv[idx] = cv;
}

// ---------------- tensor-core flash attention (causal) ----------------
#define FL_SMEM_BYTES 204288

__global__ void __launch_bounds__(256, 1) flash_tc_kernel(
    const float* __restrict__ q, const float* __restrict__ k,
    const float* __restrict__ v, float* __restrict__ o_out)
{
    extern __shared__ uint32_t sh[];
    uint32_t* Qh = sh;                    // 128*132
    uint32_t* Ql = Qh + 128 * 132;
    uint32_t* Kh = Ql + 128 * 132;        // 32*132
    uint32_t* Kl = Kh + 32 * 132;
    uint32_t* Vt = Kl + 32 * 132;         // 128*33
    uint32_t* Ps = Vt + 128 * 33;         // 128*36

    const int qb  = gridDim.x - 1 - blockIdx.x;
    const int h   = blockIdx.y, b = blockIdx.z;
    const int kvh = h >> 2;
    const int tid = threadIdx.x, warp = tid >> 5, lane = tid & 31;
    const int grp = lane >> 2, tig = lane & 3;
    const int w16 = warp * 16;
    const int rbase = qb * 128;

    {
        const float* qg = q + ((size_t)(b * SS) + rbase) * (HH * HD) + h * HD;
#pragma unroll
        for (int i = 0; i < 16; i++) {
            int f = tid + i * 256;
            int r = f >> 5, c4 = (f & 31) * 4;
            float4 t4 = *(const float4*)(qg + (size_t)r * (HH * HD) + c4);
            float va[4] = {t4.x * SCALE, t4.y * SCALE, t4.z * SCALE, t4.w * SCALE};
#pragma unroll
            for (int j = 0; j < 4; j++) {
                uint32_t hi = f2tf32(va[j]);
                Qh[r * 132 + c4 + j] = hi;
                Ql[r * 132 + c4 + j] = f2tf32(va[j] - __uint_as_float(hi));
            }
        }
    }

    float O[16][4];
#pragma unroll
    for (int nf = 0; nf < 16; nf++)
#pragma unroll
        for (int i = 0; i < 4; i++) O[nf][i] = 0.f;
    float m0 = -INFINITY, m1 = -INFINITY, l0 = 0.f, l1 = 0.f;

    const int ntiles = (qb + 1) * 4;
    for (int t = 0; t < ntiles; t++) {
        int tc0 = t * 32;
        __syncthreads();
        {
            const float* kg = k + ((size_t)(b * SS) + tc0) * (KVH * HD) + kvh * HD;
#pragma unroll
            for (int i = 0; i < 4; i++) {
                int f = tid + i * 256;
                int r = f >> 5, c4 = (f & 31) * 4;
                float4 t4 = *(const float4*)(kg + (size_t)r * (KVH * HD) + c4);
                float va[4] = {t4.x, t4.y, t4.z, t4.w};
#pragma unroll
                for (int j = 0; j < 4; j++) {
                    uint32_t hi = f2tf32(va[j]);
                    Kh[r * 132 + c4 + j] = hi;
                    Kl[r * 132 + c4 + j] = f2tf32(va[j] - __uint_as_float(hi));
                }
            }
        }
        {
            const float* vg = v + ((size_t)(b * SS) + tc0) * (KVH * HD) + kvh * HD;
#pragma unroll
            for (int i = 0; i < 4; i++) {
                int f = tid + i * 256;
                int c = f >> 5, j4 = (f & 31) * 4;
                float4 t4 = *(const float4*)(vg + (size_t)c * (KVH * HD) + j4);
                Vt[(j4 + 0) * 33 + c] = f2tf32(t4.x);
                Vt[(j4 + 1) * 33 + c] = f2tf32(t4.y);
                Vt[(j4 + 2) * 33 + c] = f2tf32(t4.z);
                Vt[(j4 + 3) * 33 + c] = f2tf32(t4.w);
            }
        }
        __syncthreads();

        float sacc[4][4];
#pragma unroll
        for (int nf = 0; nf < 4; nf++)
#pragma unroll
            for (int i = 0; i < 4; i++) sacc[nf][i] = 0.f;

#pragma unroll
        for (int ks = 0; ks < 16; ks++) {
            int kb = ks * 8;
            int ra0 = (w16 + grp) * 132 + kb + tig;
            int ra1 = (w16 + grp + 8) * 132 + kb + tig;
            uint32_t ah0 = Qh[ra0], ah1 = Qh[ra1], ah2 = Qh[ra0 + 4], ah3 = Qh[ra1 + 4];
            uint32_t al0 = Ql[ra0], al1 = Ql[ra1], al2 = Ql[ra0 + 4], al3 = Ql[ra1 + 4];
#pragma unroll
            for (int nf = 0; nf < 4; nf++) {
                int rb = (nf * 8 + grp) * 132 + kb + tig;
                uint32_t bh0 = Kh[rb], bh1 = Kh[rb + 4];
                uint32_t bl0 = Kl[rb], bl1 = Kl[rb + 4];
                MMA_TF32(sacc[nf], ah0, ah1, ah2, ah3, bh0, bh1);
                MMA_TF32(sacc[nf], ah0, ah1, ah2, ah3, bl0, bl1);
                MMA_TF32(sacc[nf], al0, al1, al2, al3, bh0, bh1);
            }
        }

        if (t >= 4 * qb) {
            int row0 = rbase + w16 + grp, row1 = row0 + 8;
#pragma unroll
            for (int nf = 0; nf < 4; nf++) {
                int col = tc0 + nf * 8 + 2 * tig;
                if (col     > row0) sacc[nf][0] = NEGV;
                if (col + 1 > row0) sacc[nf][1] = NEGV;
                if (col     > row1) sacc[nf][2] = NEGV;
                if (col + 1 > row1) sacc[nf][3] = NEGV;
            }
        }

        float mx0 = -INFINITY, mx1 = -INFINITY;
#pragma unroll
        for (int nf = 0; nf < 4; nf++) {
            mx0 = fmaxf(mx0, fmaxf(sacc[nf][0], sacc[nf][1]));
            mx1 = fmaxf(mx1, fmaxf(sacc[nf][2], sacc[nf][3]));
        }
        mx0 = fmaxf(mx0, __shfl_xor_sync(0xffffffffu, mx0, 1));
        mx0 = fmaxf(mx0, __shfl_xor_sync(0xffffffffu, mx0, 2));
        mx1 = fmaxf(mx1, __shfl_xor_sync(0xffffffffu, mx1, 1));
        mx1 = fmaxf(mx1, __shfl_xor_sync(0xffffffffu, mx1, 2));

        float nm0 = fmaxf(m0, mx0), nm1 = fmaxf(m1, mx1);
        float cr0 = __expf(m0 - nm0), cr1 = __expf(m1 - nm1);
        float s0 = 0.f, s1 = 0.f;
        int pr0 = (w16 + grp) * 36 + 2 * tig;
        int pr1 = (w16 + grp + 8) * 36 + 2 * tig;
#pragma unroll
        for (int nf = 0; nf < 4; nf++) {
            float p0 = __expf(sacc[nf][0] - nm0);
            float p1 = __expf(sacc[nf][1] - nm0);
            float p2 = __expf(sacc[nf][2] - nm1);
            float p3 = __expf(sacc[nf][3] - nm1);
            s0 += p0 + p1; s1 += p2 + p3;
            Ps[pr0 + nf * 8]     = f2tf32(p0);
            Ps[pr0 + nf * 8 + 1] = f2tf32(p1);
            Ps[pr1 + nf * 8]     = f2tf32(p2);
            Ps[pr1 + nf * 8 + 1] = f2tf32(p3);
        }
        s0 += __shfl_xor_sync(0xffffffffu, s0, 1);
        s0 += __shfl_xor_sync(0xffffffffu, s0, 2);
        s1 += __shfl_xor_sync(0xffffffffu, s1, 1);
        s1 += __shfl_xor_sync(0xffffffffu, s1, 2);
        l0 = l0 * cr0 + s0;
        l1 = l1 * cr1 + s1;
        m0 = nm0; m1 = nm1;
#pragma unroll
        for (int nf = 0; nf < 16; nf++) {
            O[nf][0] *= cr0; O[nf][1] *= cr0;
            O[nf][2] *= cr1; O[nf][3] *= cr1;
        }
        __syncwarp();

#pragma unroll
        for (int ks = 0; ks < 4; ks++) {
            int kb = ks * 8;
            int rp0 = (w16 + grp) * 36 + kb + tig;
            int rp1 = (w16 + grp + 8) * 36 + kb + tig;
            uint32_t pa0 = Ps[rp0], pa1 = Ps[rp1], pa2 = Ps[rp0 + 4], pa3 = Ps[rp1 + 4];
#pragma unroll
            for (int nf = 0; nf < 16; nf++) {
                int rv = (nf * 8 + grp) * 33 + kb + tig;
                uint32_t b0 = Vt[rv], b1 = Vt[rv + 4];
                MMA_TF32(O[nf], pa0, pa1, pa2, pa3, b0, b1);
            }
        }
        __syncwarp();
    }

    float inv0 = 1.f / l0, inv1 = 1.f / l1;
    float* og = o_out + ((size_t)(b * SS) + rbase + w16) * (HH * HD) + h * HD;
#pragma unroll
    for (int nf = 0; nf < 16; nf++) {
        int col = nf * 8 + 2 * tig;
        *(float2*)(og + (size_t)grp * (HH * HD) + col) =
            make_float2(O[nf][0] * inv0, O[nf][1] * inv0);
        *(float2*)(og + (size_t)(grp + 8) * (HH * HD) + col) =
            make_float2(O[nf][2] * inv1, O[nf][3] * inv1);
    }
}

// ---------------- launch ----------------
extern "C" void kernel_launch(void* const* d_in, const int* in_sizes, int n_in,
                              void* d_out, int out_size)
{
    const float* x    = (const float*)d_in[0];
    const float* cosf = (const float*)d_in[1];
    const float* sinf = (const float*)d_in[2];
    const float* ck_in = (const float*)d_in[5];
    const float* cv_in = (const float*)d_in[6];
    const float* wq   = (const float*)d_in[7];
    const float* wk   = (const float*)d_in[8];
    const float* wv   = (const float*)d_in[9];
    const float* wo   = (const float*)d_in[10];

    float* out   = (float*)d_out;
    float* outck = out + (size_t)MM * (HH * HD);
    float* outcv = outck + (size_t)BB * SWW * KVH * HD;

    float* q = nullptr; cudaGetSymbolAddress((void**)&q, g_q);
    float* k = nullptr; cudaGetSymbolAddress((void**)&k, g_k);
    float* v = nullptr; cudaGetSymbolAddress((void**)&v, g_v);
    float* a = nullptr; cudaGetSymbolAddress((void**)&a, g_attn);

    static bool attr_done = false;
    if (!attr_done) {
        cudaFuncSetAttribute(flash_tc_kernel,
                             cudaFuncAttributeMaxDynamicSharedMemorySize, FL_SMEM_BYTES);
        cudaFuncSetAttribute(gemm_tf32_db_kernel,
                             cudaFuncAttributeMaxDynamicSharedMemorySize, G1_SMEM);
        cudaFuncSetAttribute(gemm_tf32x3_db_kernel,
                             cudaFuncAttributeMaxDynamicSharedMemorySize, G3_SMEM);
        attr_done = true;
    }

    // Q projection (single-pass tf32, double-buffered)
    gemm_tf32_db_kernel<<<dim3((HH*HD)/128,  MM/128), 256, G1_SMEM>>>(x, wq, q, MM, HH*HD, DD);
    // K/V projections (split-tf32 x3, double-buffered)
    gemm_tf32x3_db_kernel<<<dim3((KVH*HD)/128, MM/128), 256, G3_SMEM>>>(x, wk, k, MM, KVH*HD, DD);
    gemm_tf32x3_db_kernel<<<dim3((KVH*HD)/128, MM/128), 256, G3_SMEM>>>(x, wv, v, MM, KVH*HD, DD);

    // RoPE
    {
        int tq = MM * HH * 64;
        rope_kernel<<<(tq + 255) / 256, 256>>>(q, cosf, sinf, HH);
        int tk = MM * KVH * 64;
        rope_kernel<<<(tk + 255) / 256, 256>>>(k, cosf, sinf, KVH);
    }

    // KV cache write-back
    {
        int total = BB * SWW * KVH * HD;
        cache_kernel<<<(total + 255) / 256, 256>>>(k, v, ck_in, cv_in, outck, outcv);
    }

    // tensor-core causal flash attention
    flash_tc_kernel<<<dim3(SS / 128, HH, BB), 256, FL_SMEM_BYTES>>>(q, k, v, a);

    // output projection (single-pass tf32, double-buffered)
    gemm_tf32_db_kernel<<<dim3((HH*HD)/128, MM/128), 256, G1_SMEM>>>(a, wo, out, MM, HH*HD, DD);
}

// round 5
// speedup vs baseline: 3.2801x; 1.1409x over previous
#include <cuda_runtime.h>
#include <math.h>
#include <stdint.h>

// Problem constants
#define BB   2
#define SS   2048
#define DD   4096
#define HH   32
#define KVH  8
#define HD   128
#define SWW  4096
#define MM   (BB*SS)          // 4096 rows
#define NEGV (-1.0e9f)
#define SCALE (0.08838834764831845f)  // 128^-0.5

// ---------------- scratch (module-static, no runtime alloc) ----------------
__device__ float g_q[(size_t)MM * (HH*HD)];      // 4096 x 4096
__device__ float g_k[(size_t)MM * (KVH*HD)];     // 4096 x 1024
__device__ float g_v[(size_t)MM * (KVH*HD)];     // 4096 x 1024
__device__ float g_attn[(size_t)MM * (HH*HD)];   // 4096 x 4096

__device__ __forceinline__ uint32_t f2tf32(float f) {
    uint32_t r;
    asm("cvt.rna.tf32.f32 %0, %1;" : "=r"(r) : "f"(f));
    return r;
}

#define MMA_TF32(d, a0,a1,a2,a3, b0,b1) \
    asm volatile("mma.sync.aligned.m16n8k8.row.col.f32.tf32.tf32.f32 " \
        "{%0,%1,%2,%3}, {%4,%5,%6,%7}, {%8,%9}, {%0,%1,%2,%3};" \
        : "+f"(d[0]),"+f"(d[1]),"+f"(d[2]),"+f"(d[3]) \
        : "r"(a0),"r"(a1),"r"(a2),"r"(a3),"r"(b0),"r"(b1))

// ================= TF32 GEMM, register-staged double buffering =============
// C[M,N] = A[M,K] @ B[K,N], row-major. Block 128x128x32, 8 warps.
#define G1_STAGE 8960
#define G1_SMEM  (2 * G1_STAGE * 4)

__global__ void __launch_bounds__(256) gemm_tf32_db_kernel(
    const float* __restrict__ A, const float* __restrict__ B,
    float* __restrict__ C, int M, int N, int K)
{
    extern __shared__ uint32_t sm[];

    const int tid  = threadIdx.x;
    const int warp = tid >> 5;
    const int lane = tid & 31;
    const int grp  = lane >> 2;
    const int tig  = lane & 3;
    const int warp_m = warp & 3;
    const int warp_n = warp >> 2;

    const int brow = blockIdx.y, bcol = blockIdx.x;

    const float* Ap = A + (size_t)brow * 128 * K;
    const float* Bp = B + bcol * 128;

    float acc[2][8][4];
#pragma unroll
    for (int mt = 0; mt < 2; mt++)
#pragma unroll
        for (int nt = 0; nt < 8; nt++)
#pragma unroll
            for (int i = 0; i < 4; i++) acc[mt][nt][i] = 0.f;

    float4 ra[4]; float4 rb[4];
#pragma unroll
    for (int i = 0; i < 4; i++) {
        int idx = tid + i * 256;
        ra[i] = *(const float4*)(Ap + (size_t)(idx >> 3) * K + ((idx & 7) * 4));
        rb[i] = *(const float4*)(Bp + (size_t)(idx >> 5) * N + ((idx & 31) * 4));
    }
    {
        uint32_t* As = sm; uint32_t* Bs = sm + 128 * 36;
#pragma unroll
        for (int i = 0; i < 4; i++) {
            int idx = tid + i * 256;
            int r = idx >> 3, c = (idx & 7) * 4;
            uint4 t; t.x = f2tf32(ra[i].x); t.y = f2tf32(ra[i].y);
            t.z = f2tf32(ra[i].z); t.w = f2tf32(ra[i].w);
            *(uint4*)&As[r * 36 + c] = t;
            int r2 = idx >> 5, c2 = (idx & 31) * 4;
            uint4 u; u.x = f2tf32(rb[i].x); u.y = f2tf32(rb[i].y);
            u.z = f2tf32(rb[i].z); u.w = f2tf32(rb[i].w);
            *(uint4*)&Bs[r2 * 136 + c2] = u;
        }
    }
    __syncthreads();

    const int nk = K >> 5;
    for (int kt = 0; kt < nk; kt++) {
        if (kt + 1 < nk) {
            int k0 = (kt + 1) << 5;
#pragma unroll
            for (int i = 0; i < 4; i++) {
                int idx = tid + i * 256;
                ra[i] = *(const float4*)(Ap + (size_t)(idx >> 3) * K + k0 + ((idx & 7) * 4));
                rb[i] = *(const float4*)(Bp + (size_t)(k0 + (idx >> 5)) * N + ((idx & 31) * 4));
            }
        }
        {
            uint32_t* As = sm + (kt & 1) * G1_STAGE;
            uint32_t* Bs = As + 128 * 36;
#pragma unroll
            for (int ks = 0; ks < 4; ks++) {
                int kb = ks * 8;
                uint32_t af[2][4], bf[8][2];
#pragma unroll
                for (int mt = 0; mt < 2; mt++) {
                    int row0 = warp_m * 32 + mt * 16 + grp;
                    af[mt][0] = As[row0 * 36 + kb + tig];
                    af[mt][1] = As[(row0 + 8) * 36 + kb + tig];
                    af[mt][2] = As[row0 * 36 + kb + 4 + tig];
                    af[mt][3] = As[(row0 + 8) * 36 + kb + 4 + tig];
                }
#pragma unroll
                for (int nt = 0; nt < 8; nt++) {
                    int colw = warp_n * 64 + nt * 8 + grp;
                    bf[nt][0] = Bs[(kb + tig) * 136 + colw];
                    bf[nt][1] = Bs[(kb + 4 + tig) * 136 + colw];
                }
#pragma unroll
                for (int mt = 0; mt < 2; mt++)
#pragma unroll
                    for (int nt = 0; nt < 8; nt++)
                        MMA_TF32(acc[mt][nt], af[mt][0], af[mt][1], af[mt][2], af[mt][3],
                                 bf[nt][0], bf[nt][1]);
            }
        }
        if (kt + 1 < nk) {
            uint32_t* As = sm + ((kt + 1) & 1) * G1_STAGE;
            uint32_t* Bs = As + 128 * 36;
#pragma unroll
            for (int i = 0; i < 4; i++) {
                int idx = tid + i * 256;
                int r = idx >> 3, c = (idx & 7) * 4;
                uint4 t; t.x = f2tf32(ra[i].x); t.y = f2tf32(ra[i].y);
                t.z = f2tf32(ra[i].z); t.w = f2tf32(ra[i].w);
                *(uint4*)&As[r * 36 + c] = t;
                int r2 = idx >> 5, c2 = (idx & 31) * 4;
                uint4 u; u.x = f2tf32(rb[i].x); u.y = f2tf32(rb[i].y);
                u.z = f2tf32(rb[i].z); u.w = f2tf32(rb[i].w);
                *(uint4*)&Bs[r2 * 136 + c2] = u;
            }
        }
        __syncthreads();
    }

#pragma unroll
    for (int mt = 0; mt < 2; mt++) {
        int row = brow * 128 + warp_m * 32 + mt * 16 + grp;
#pragma unroll
        for (int nt = 0; nt < 8; nt++) {
            int col = bcol * 128 + warp_n * 64 + nt * 8 + tig * 2;
            *(float2*)(C + (size_t)row * N + col) =
                make_float2(acc[mt][nt][0], acc[mt][nt][1]);
            *(float2*)(C + (size_t)(row + 8) * N + col) =
                make_float2(acc[mt][nt][2], acc[mt][nt][3]);
        }
    }
}

// ---------------- RoPE (in place) ----------------
__global__ void rope_kernel(float* __restrict__ buf,
                            const float* __restrict__ cosf,
                            const float* __restrict__ sinf,
                            int heads)
{
    int idx = blockIdx.x * blockDim.x + threadIdx.x;
    int total = MM * heads * (HD / 2);
    if (idx >= total) return;
    int i   = idx & 63;
    int t   = idx >> 6;
    int h   = t % heads;
    int row = t / heads;
    int s   = row & (SS - 1);
    float c  = cosf[s * 64 + i];
    float sn = sinf[s * 64 + i];
    float* p = buf + (size_t)row * heads * HD + h * HD + 2 * i;
    float x1 = p[0], x2 = p[1];
    p[0] = x1 * c - x2 * sn;
    p[1] = x1 * sn + x2 * c;
}

// ---------------- cache write-back ----------------
__global__ void cache_kernel(const float* __restrict__ kbuf,
                             const float* __restrict__ vbuf,
                             const float* __restrict__ ck_in,
                             const float* __restrict__ cv_in,
                             float* __restrict__ out_ck,
                             float* __restrict__ out_cv)
{
    int idx = blockIdx.x * blockDim.x + threadIdx.x;
    const int total = BB * SWW * KVH * HD;
    if (idx >= total) return;
    int d = idx & 1023;
    int t = (idx >> 10) & (SWW - 1);
    int b = idx >> 22;
    float ck = ck_in[idx];
    float cv = cv_in[idx];
    if (t < SS) {
        float xk = kbuf[(size_t)(b * SS + t) * (KVH * HD) + d];
        float xv = vbuf[(size_t)(b * SS + t) * (KVH * HD) + d];
        ck = (xk != 0.f) ? xk : ck;
        cv = (xv != 0.f) ? xv : cv;
    }
    out_ck[idx] = ck;
    out_cv[idx] = cv;
}

// ---------------- tensor-core flash attention (causal) ----------------
#define FL_SMEM_BYTES 204288

__global__ void __launch_bounds__(256, 1) flash_tc_kernel(
    const float* __restrict__ q, const float* __restrict__ k,
    const float* __restrict__ v, float* __restrict__ o_out)
{
    extern __shared__ uint32_t sh[];
    uint32_t* Qh = sh;                    // 128*132
    uint32_t* Ql = Qh + 128 * 132;
    uint32_t* Kh = Ql + 128 * 132;        // 32*132
    uint32_t* Kl = Kh + 32 * 132;
    uint32_t* Vt = Kl + 32 * 132;         // 128*33
    uint32_t* Ps = Vt + 128 * 33;         // 128*36

    const int qb  = gridDim.x - 1 - blockIdx.x;
    const int h   = blockIdx.y, b = blockIdx.z;
    const int kvh = h >> 2;
    const int tid = threadIdx.x, warp = tid >> 5, lane = tid & 31;
    const int grp = lane >> 2, tig = lane & 3;
    const int w16 = warp * 16;
    const int rbase = qb * 128;

    {
        const float* qg = q + ((size_t)(b * SS) + rbase) * (HH * HD) + h * HD;
#pragma unroll
        for (int i = 0; i < 16; i++) {
            int f = tid + i * 256;
            int r = f >> 5, c4 = (f & 31) * 4;
            float4 t4 = *(const float4*)(qg + (size_t)r * (HH * HD) + c4);
            float va[4] = {t4.x * SCALE, t4.y * SCALE, t4.z * SCALE, t4.w * SCALE};
#pragma unroll
            for (int j = 0; j < 4; j++) {
                uint32_t hi = f2tf32(va[j]);
                Qh[r * 132 + c4 + j] = hi;
                Ql[r * 132 + c4 + j] = f2tf32(va[j] - __uint_as_float(hi));
            }
        }
    }

    float O[16][4];
#pragma unroll
    for (int nf = 0; nf < 16; nf++)
#pragma unroll
        for (int i = 0; i < 4; i++) O[nf][i] = 0.f;
    float m0 = -INFINITY, m1 = -INFINITY, l0 = 0.f, l1 = 0.f;

    const int ntiles = (qb + 1) * 4;
    for (int t = 0; t < ntiles; t++) {
        int tc0 = t * 32;
        __syncthreads();
        {
            const float* kg = k + ((size_t)(b * SS) + tc0) * (KVH * HD) + kvh * HD;
#pragma unroll
            for (int i = 0; i < 4; i++) {
                int f = tid + i * 256;
                int r = f >> 5, c4 = (f & 31) * 4;
                float4 t4 = *(const float4*)(kg + (size_t)r * (KVH * HD) + c4);
                float va[4] = {t4.x, t4.y, t4.z, t4.w};
#pragma unroll
                for (int j = 0; j < 4; j++) {
                    uint32_t hi = f2tf32(va[j]);
                    Kh[r * 132 + c4 + j] = hi;
                    Kl[r * 132 + c4 + j] = f2tf32(va[j] - __uint_as_float(hi));
                }
            }
        }
        {
            const float* vg = v + ((size_t)(b * SS) + tc0) * (KVH * HD) + kvh * HD;
#pragma unroll
            for (int i = 0; i < 4; i++) {
                int f = tid + i * 256;
                int c = f >> 5, j4 = (f & 31) * 4;
                float4 t4 = *(const float4*)(vg + (size_t)c * (KVH * HD) + j4);
                Vt[(j4 + 0) * 33 + c] = f2tf32(t4.x);
                Vt[(j4 + 1) * 33 + c] = f2tf32(t4.y);
                Vt[(j4 + 2) * 33 + c] = f2tf32(t4.z);
                Vt[(j4 + 3) * 33 + c] = f2tf32(t4.w);
            }
        }
        __syncthreads();

        float sacc[4][4];
#pragma unroll
        for (int nf = 0; nf < 4; nf++)
#pragma unroll
            for (int i = 0; i < 4; i++) sacc[nf][i] = 0.f;

#pragma unroll
        for (int ks = 0; ks < 16; ks++) {
            int kb = ks * 8;
            int ra0 = (w16 + grp) * 132 + kb + tig;
            int ra1 = (w16 + grp + 8) * 132 + kb + tig;
            uint32_t ah0 = Qh[ra0], ah1 = Qh[ra1], ah2 = Qh[ra0 + 4], ah3 = Qh[ra1 + 4];
            uint32_t al0 = Ql[ra0], al1 = Ql[ra1], al2 = Ql[ra0 + 4], al3 = Ql[ra1 + 4];
#pragma unroll
            for (int nf = 0; nf < 4; nf++) {
                int rb = (nf * 8 + grp) * 132 + kb + tig;
                uint32_t bh0 = Kh[rb], bh1 = Kh[rb + 4];
                uint32_t bl0 = Kl[rb], bl1 = Kl[rb + 4];
                MMA_TF32(sacc[nf], ah0, ah1, ah2, ah3, bh0, bh1);
                MMA_TF32(sacc[nf], ah0, ah1, ah2, ah3, bl0, bl1);
                MMA_TF32(sacc[nf], al0, al1, al2, al3, bh0, bh1);
            }
        }

        if (t >= 4 * qb) {
            int row0 = rbase + w16 + grp, row1 = row0 + 8;
#pragma unroll
            for (int nf = 0; nf < 4; nf++) {
                int col = tc0 + nf * 8 + 2 * tig;
                if (col     > row0) sacc[nf][0] = NEGV;
                if (col + 1 > row0) sacc[nf][1] = NEGV;
                if (col     > row1) sacc[nf][2] = NEGV;
                if (col + 1 > row1) sacc[nf][3] = NEGV;
            }
        }

        float mx0 = -INFINITY, mx1 = -INFINITY;
#pragma unroll
        for (int nf = 0; nf < 4; nf++) {
            mx0 = fmaxf(mx0, fmaxf(sacc[nf][0], sacc[nf][1]));
            mx1 = fmaxf(mx1, fmaxf(sacc[nf][2], sacc[nf][3]));
        }
        mx0 = fmaxf(mx0, __shfl_xor_sync(0xffffffffu, mx0, 1));
        mx0 = fmaxf(mx0, __shfl_xor_sync(0xffffffffu, mx0, 2));
        mx1 = fmaxf(mx1, __shfl_xor_sync(0xffffffffu, mx1, 1));
        mx1 = fmaxf(mx1, __shfl_xor_sync(0xffffffffu, mx1, 2));

        float nm0 = fmaxf(m0, mx0), nm1 = fmaxf(m1, mx1);
        float cr0 = __expf(m0 - nm0), cr1 = __expf(m1 - nm1);
        float s0 = 0.f, s1 = 0.f;
        int pr0 = (w16 + grp) * 36 + 2 * tig;
        int pr1 = (w16 + grp + 8) * 36 + 2 * tig;
#pragma unroll
        for (int nf = 0; nf < 4; nf++) {
            float p0 = __expf(sacc[nf][0] - nm0);
            float p1 = __expf(sacc[nf][1] - nm0);
            float p2 = __expf(sacc[nf][2] - nm1);
            float p3 = __expf(sacc[nf][3] - nm1);
            s0 += p0 + p1; s1 += p2 + p3;
            Ps[pr0 + nf * 8]     = f2tf32(p0);
            Ps[pr0 + nf * 8 + 1] = f2tf32(p1);
            Ps[pr1 + nf * 8]     = f2tf32(p2);
            Ps[pr1 + nf * 8 + 1] = f2tf32(p3);
        }
        s0 += __shfl_xor_sync(0xffffffffu, s0, 1);
        s0 += __shfl_xor_sync(0xffffffffu, s0, 2);
        s1 += __shfl_xor_sync(0xffffffffu, s1, 1);
        s1 += __shfl_xor_sync(0xffffffffu, s1, 2);
        l0 = l0 * cr0 + s0;
        l1 = l1 * cr1 + s1;
        m0 = nm0; m1 = nm1;
#pragma unroll
        for (int nf = 0; nf < 16; nf++) {
            O[nf][0] *= cr0; O[nf][1] *= cr0;
            O[nf][2] *= cr1; O[nf][3] *= cr1;
        }
        __syncwarp();

#pragma unroll
        for (int ks = 0; ks < 4; ks++) {
            int kb = ks * 8;
            int rp0 = (w16 + grp) * 36 + kb + tig;
            int rp1 = (w16 + grp + 8) * 36 + kb + tig;
            uint32_t pa0 = Ps[rp0], pa1 = Ps[rp1], pa2 = Ps[rp0 + 4], pa3 = Ps[rp1 + 4];
#pragma unroll
            for (int nf = 0; nf < 16; nf++) {
                int rv = (nf * 8 + grp) * 33 + kb + tig;
                uint32_t b0 = Vt[rv], b1 = Vt[rv + 4];
                MMA_TF32(O[nf], pa0, pa1, pa2, pa3, b0, b1);
            }
        }
        __syncwarp();
    }

    float inv0 = 1.f / l0, inv1 = 1.f / l1;
    float* og = o_out + ((size_t)(b * SS) + rbase + w16) * (HH * HD) + h * HD;
#pragma unroll
    for (int nf = 0; nf < 16; nf++) {
        int col = nf * 8 + 2 * tig;
        *(float2*)(og + (size_t)grp * (HH * HD) + col) =
            make_float2(O[nf][0] * inv0, O[nf][1] * inv0);
        *(float2*)(og + (size_t)(grp + 8) * (HH * HD) + col) =
            make_float2(O[nf][2] * inv1, O[nf][3] * inv1);
    }
}

// ---------------- launch ----------------
extern "C" void kernel_launch(void* const* d_in, const int* in_sizes, int n_in,
                              void* d_out, int out_size)
{
    const float* x    = (const float*)d_in[0];
    const float* cosf = (const float*)d_in[1];
    const float* sinf = (const float*)d_in[2];
    const float* ck_in = (const float*)d_in[5];
    const float* cv_in = (const float*)d_in[6];
    const float* wq   = (const float*)d_in[7];
    const float* wk   = (const float*)d_in[8];
    const float* wv   = (const float*)d_in[9];
    const float* wo   = (const float*)d_in[10];

    float* out   = (float*)d_out;
    float* outck = out + (size_t)MM * (HH * HD);
    float* outcv = outck + (size_t)BB * SWW * KVH * HD;

    float* q = nullptr; cudaGetSymbolAddress((void**)&q, g_q);
    float* k = nullptr; cudaGetSymbolAddress((void**)&k, g_k);
    float* v = nullptr; cudaGetSymbolAddress((void**)&v, g_v);
    float* a = nullptr; cudaGetSymbolAddress((void**)&a, g_attn);

    static bool attr_done = false;
    if (!attr_done) {
        cudaFuncSetAttribute(flash_tc_kernel,
                             cudaFuncAttributeMaxDynamicSharedMemorySize, FL_SMEM_BYTES);
        cudaFuncSetAttribute(gemm_tf32_db_kernel,
                             cudaFuncAttributeMaxDynamicSharedMemorySize, G1_SMEM);
        attr_done = true;
    }

    // QKV projections (single-pass tf32, double-buffered)
    gemm_tf32_db_kernel<<<dim3((HH*HD)/128,  MM/128), 256, G1_SMEM>>>(x, wq, q, MM, HH*HD, DD);
    gemm_tf32_db_kernel<<<dim3((KVH*HD)/128, MM/128), 256, G1_SMEM>>>(x, wk, k, MM, KVH*HD, DD);
    gemm_tf32_db_kernel<<<dim3((KVH*HD)/128, MM/128), 256, G1_SMEM>>>(x, wv, v, MM, KVH*HD, DD);

    // RoPE
    {
        int tq = MM * HH * 64;
        rope_kernel<<<(tq + 255) / 256, 256>>>(q, cosf, sinf, HH);
        int tk = MM * KVH * 64;
        rope_kernel<<<(tk + 255) / 256, 256>>>(k, cosf, sinf, KVH);
    }

    // KV cache write-back
    {
        int total = BB * SWW * KVH * HD;
        cache_kernel<<<(total + 255) / 256, 256>>>(k, v, ck_in, cv_in, outck, outcv);
    }

    // tensor-core causal flash attention
    flash_tc_kernel<<<dim3(SS / 128, HH, BB), 256, FL_SMEM_BYTES>>>(q, k, v, a);

    // output projection (single-pass tf32, double-buffered)
    gemm_tf32_db_kernel<<<dim3((HH*HD)/128, MM/128), 256, G1_SMEM>>>(a, wo, out, MM, HH*HD, DD);
}

// round 8
// speedup vs baseline: 3.9893x; 1.2162x over previous
#include <cuda_runtime.h>
#include <cuda_bf16.h>
#include <math.h>
#include <stdint.h>

// Problem constants
#define BB   2
#define SS   2048
#define DD   4096
#define HH   32
#define KVH  8
#define HD   128
#define SWW  4096
#define MM   (BB*SS)          // 4096 rows
#define NEGV (-1.0e9f)
#define SCALE (0.08838834764831845f)  // 128^-0.5

// ---------------- scratch (module-static, no runtime alloc) ----------------
__device__ float g_q[(size_t)MM * (HH*HD)];      // 4096 x 4096
__device__ float g_k[(size_t)MM * (KVH*HD)];     // 4096 x 1024
__device__ float g_v[(size_t)MM * (KVH*HD)];     // 4096 x 1024
__device__ float g_attn[(size_t)MM * (HH*HD)];   // 4096 x 4096

__device__ __forceinline__ uint32_t f2tf32(float f) {
    uint32_t r;
    asm("cvt.rna.tf32.f32 %0, %1;" : "=r"(r) : "f"(f));
    return r;
}
// pack (x -> low half, y -> high half) as bf16x2
__device__ __forceinline__ uint32_t pack_bf16(float x, float y) {
    uint32_t r;
    asm("cvt.rn.bf16x2.f32 %0, %1, %2;" : "=r"(r) : "f"(y), "f"(x));
    return r;
}
__device__ __forceinline__ float bf16_round(float x) {
    return __bfloat162float(__float2bfloat16(x));
}

#define MMA_TF32(d, a0,a1,a2,a3, b0,b1) \
    asm volatile("mma.sync.aligned.m16n8k8.row.col.f32.tf32.tf32.f32 " \
        "{%0,%1,%2,%3}, {%4,%5,%6,%7}, {%8,%9}, {%0,%1,%2,%3};" \
        : "+f"(d[0]),"+f"(d[1]),"+f"(d[2]),"+f"(d[3]) \
        : "r"(a0),"r"(a1),"r"(a2),"r"(a3),"r"(b0),"r"(b1))

#define MMA_BF16(d, a0,a1,a2,a3, b0,b1) \
    asm volatile("mma.sync.aligned.m16n8k16.row.col.f32.bf16.bf16.f32 " \
        "{%0,%1,%2,%3}, {%4,%5,%6,%7}, {%8,%9}, {%0,%1,%2,%3};" \
        : "+f"(d[0]),"+f"(d[1]),"+f"(d[2]),"+f"(d[3]) \
        : "r"(a0),"r"(a1),"r"(a2),"r"(a3),"r"(b0),"r"(b1))

// ================= TF32 GEMM, register-staged double buffering =============
#define G1_STAGE 8960
#define G1_SMEM  (2 * G1_STAGE * 4)

__global__ void __launch_bounds__(256) gemm_tf32_db_kernel(
    const float* __restrict__ A, const float* __restrict__ B,
    float* __restrict__ C, int M, int N, int K)
{
    extern __shared__ uint32_t sm[];

    const int tid  = threadIdx.x;
    const int warp = tid >> 5;
    const int lane = tid & 31;
    const int grp  = lane >> 2;
    const int tig  = lane & 3;
    const int warp_m = warp & 3;
    const int warp_n = warp >> 2;

    const int brow = blockIdx.y, bcol = blockIdx.x;

    const float* Ap = A + (size_t)brow * 128 * K;
    const float* Bp = B + bcol * 128;

    float acc[2][8][4];
#pragma unroll
    for (int mt = 0; mt < 2; mt++)
#pragma unroll
        for (int nt = 0; nt < 8; nt++)
#pragma unroll
            for (int i = 0; i < 4; i++) acc[mt][nt][i] = 0.f;

    float4 ra[4]; float4 rb[4];
#pragma unroll
    for (int i = 0; i < 4; i++) {
        int idx = tid + i * 256;
        ra[i] = *(const float4*)(Ap + (size_t)(idx >> 3) * K + ((idx & 7) * 4));
        rb[i] = *(const float4*)(Bp + (size_t)(idx >> 5) * N + ((idx & 31) * 4));
    }
    {
        uint32_t* As = sm; uint32_t* Bs = sm + 128 * 36;
#pragma unroll
        for (int i = 0; i < 4; i++) {
            int idx = tid + i * 256;
            int r = idx >> 3, c = (idx & 7) * 4;
            uint4 t; t.x = f2tf32(ra[i].x); t.y = f2tf32(ra[i].y);
            t.z = f2tf32(ra[i].z); t.w = f2tf32(ra[i].w);
            *(uint4*)&As[r * 36 + c] = t;
            int r2 = idx >> 5, c2 = (idx & 31) * 4;
            uint4 u; u.x = f2tf32(rb[i].x); u.y = f2tf32(rb[i].y);
            u.z = f2tf32(rb[i].z); u.w = f2tf32(rb[i].w);
            *(uint4*)&Bs[r2 * 136 + c2] = u;
        }
    }
    __syncthreads();

    const int nk = K >> 5;
    for (int kt = 0; kt < nk; kt++) {
        if (kt + 1 < nk) {
            int k0 = (kt + 1) << 5;
#pragma unroll
            for (int i = 0; i < 4; i++) {
                int idx = tid + i * 256;
                ra[i] = *(const float4*)(Ap + (size_t)(idx >> 3) * K + k0 + ((idx & 7) * 4));
                rb[i] = *(const float4*)(Bp + (size_t)(k0 + (idx >> 5)) * N + ((idx & 31) * 4));
            }
        }
        {
            uint32_t* As = sm + (kt & 1) * G1_STAGE;
            uint32_t* Bs = As + 128 * 36;
#pragma unroll
            for (int ks = 0; ks < 4; ks++) {
                int kb = ks * 8;
                uint32_t af[2][4], bf[8][2];
#pragma unroll
                for (int mt = 0; mt < 2; mt++) {
                    int row0 = warp_m * 32 + mt * 16 + grp;
                    af[mt][0] = As[row0 * 36 + kb + tig];
                    af[mt][1] = As[(row0 + 8) * 36 + kb + tig];
                    af[mt][2] = As[row0 * 36 + kb + 4 + tig];
                    af[mt][3] = As[(row0 + 8) * 36 + kb + 4 + tig];
                }
#pragma unroll
                for (int nt = 0; nt < 8; nt++) {
                    int colw = warp_n * 64 + nt * 8 + grp;
                    bf[nt][0] = Bs[(kb + tig) * 136 + colw];
                    bf[nt][1] = Bs[(kb + 4 + tig) * 136 + colw];
                }
#pragma unroll
                for (int mt = 0; mt < 2; mt++)
#pragma unroll
                    for (int nt = 0; nt < 8; nt++)
                        MMA_TF32(acc[mt][nt], af[mt][0], af[mt][1], af[mt][2], af[mt][3],
                                 bf[nt][0], bf[nt][1]);
            }
        }
        if (kt + 1 < nk) {
            uint32_t* As = sm + ((kt + 1) & 1) * G1_STAGE;
            uint32_t* Bs = As + 128 * 36;
#pragma unroll
            for (int i = 0; i < 4; i++) {
                int idx = tid + i * 256;
                int r = idx >> 3, c = (idx & 7) * 4;
                uint4 t; t.x = f2tf32(ra[i].x); t.y = f2tf32(ra[i].y);
                t.z = f2tf32(ra[i].z); t.w = f2tf32(ra[i].w);
                *(uint4*)&As[r * 36 + c] = t;
                int r2 = idx >> 5, c2 = (idx & 31) * 4;
                uint4 u; u.x = f2tf32(rb[i].x); u.y = f2tf32(rb[i].y);
                u.z = f2tf32(rb[i].z); u.w = f2tf32(rb[i].w);
                *(uint4*)&Bs[r2 * 136 + c2] = u;
            }
        }
        __syncthreads();
    }

#pragma unroll
    for (int mt = 0; mt < 2; mt++) {
        int row = brow * 128 + warp_m * 32 + mt * 16 + grp;
#pragma unroll
        for (int nt = 0; nt < 8; nt++) {
            int col = bcol * 128 + warp_n * 64 + nt * 8 + tig * 2;
            *(float2*)(C + (size_t)row * N + col) =
                make_float2(acc[mt][nt][0], acc[mt][nt][1]);
            *(float2*)(C + (size_t)(row + 8) * N + col) =
                make_float2(acc[mt][nt][2], acc[mt][nt][3]);
        }
    }
}

// ---------------- RoPE (in place) ----------------
__global__ void rope_kernel(float* __restrict__ buf,
                            const float* __restrict__ cosf,
                            const float* __restrict__ sinf,
                            int heads)
{
    int idx = blockIdx.x * blockDim.x + threadIdx.x;
    int total = MM * heads * (HD / 2);
    if (idx >= total) return;
    int i   = idx & 63;
    int t   = idx >> 6;
    int h   = t % heads;
    int row = t / heads;
    int s   = row & (SS - 1);
    float c  = cosf[s * 64 + i];
    float sn = sinf[s * 64 + i];
    float* p = buf + (size_t)row * heads * HD + h * HD + 2 * i;
    float x1 = p[0], x2 = p[1];
    p[0] = x1 * c - x2 * sn;
    p[1] = x1 * sn + x2 * c;
}

// ---------------- cache write-back ----------------
__global__ void cache_kernel(const float* __restrict__ kbuf,
                             const float* __restrict__ vbuf,
                             const float* __restrict__ ck_in,
                             const float* __restrict__ cv_in,
                             float* __restrict__ out_ck,
                             float* __restrict__ out_cv)
{
    int idx = blockIdx.x * blockDim.x + threadIdx.x;
    const int total = BB * SWW * KVH * HD;
    if (idx >= total) return;
    int d = idx & 1023;
    int t = (idx >> 10) & (SWW - 1);
    int b = idx >> 22;
    float ck = ck_in[idx];
    float cv = cv_in[idx];
    if (t < SS) {
        float xk = kbuf[(size_t)(b * SS + t) * (KVH * HD) + d];
        float xv = vbuf[(size_t)(b * SS + t) * (KVH * HD) + d];
        ck = (xk != 0.f) ? xk : ck;
        cv = (xv != 0.f) ? xv : cv;
    }
    out_ck[idx] = ck;
    out_cv[idx] = cv;
}

// ---------------- tensor-core flash attention (causal) ----------------
// Br=128 (8 warps x 16 rows), Bc=32.
// QK^T: split-bf16 (3x m16n8k16) — halves QK MMA issue vs tf32x3.
// PV: single tf32 m16n8k8, V stored NATIVE [c][d] (no transpose).
// K/V of next tile prefetched into registers during compute.
// smem words: Qh 128*68, Ql 128*68, Kh 32*68, Kl 32*68, Vs 32*136, Ps 128*36
#define FL_SMEM_BYTES ((128*68*2 + 32*68*2 + 32*136 + 128*36) * 4)  // 122880

__global__ void __launch_bounds__(256, 1) flash_tc_kernel(
    const float* __restrict__ q, const float* __restrict__ k,
    const float* __restrict__ v, float* __restrict__ o_out)
{
    extern __shared__ uint32_t sh[];
    uint32_t* Qh = sh;                    // 128*68 (bf16x2 words)
    uint32_t* Ql = Qh + 128 * 68;
    uint32_t* Kh = Ql + 128 * 68;         // 32*68
    uint32_t* Kl = Kh + 32 * 68;
    uint32_t* Vs = Kl + 32 * 68;          // 32*136 (tf32, native [c][d])
    uint32_t* Ps = Vs + 32 * 136;         // 128*36

    const int qb  = gridDim.x - 1 - blockIdx.x;   // heavy blocks first
    const int h   = blockIdx.y, b = blockIdx.z;
    const int kvh = h >> 2;
    const int tid = threadIdx.x, warp = tid >> 5, lane = tid & 31;
    const int grp = lane >> 2, tig = lane & 3;
    const int w16 = warp * 16;
    const int rbase = qb * 128;

    const float* kg = k + (size_t)(b * SS) * (KVH * HD) + kvh * HD;
    const float* vg = v + (size_t)(b * SS) * (KVH * HD) + kvh * HD;

    // ---- load Q tile (scaled, split hi/lo bf16) ----
    {
        const float* qg = q + ((size_t)(b * SS) + rbase) * (HH * HD) + h * HD;
#pragma unroll
        for (int i = 0; i < 16; i++) {
            int f = tid + i * 256;
            int r = f >> 5, c4 = (f & 31) * 4;
            float4 t4 = *(const float4*)(qg + (size_t)r * (HH * HD) + c4);
            float x0 = t4.x * SCALE, x1 = t4.y * SCALE, x2 = t4.z * SCALE, x3 = t4.w * SCALE;
            float h0 = bf16_round(x0), h1 = bf16_round(x1);
            float h2 = bf16_round(x2), h3 = bf16_round(x3);
            uint2 wh = make_uint2(pack_bf16(h0, h1), pack_bf16(h2, h3));
            uint2 wl = make_uint2(pack_bf16(x0 - h0, x1 - h1), pack_bf16(x2 - h2, x3 - h3));
            *(uint2*)&Qh[r * 68 + (f & 31) * 2] = wh;
            *(uint2*)&Ql[r * 68 + (f & 31) * 2] = wl;
        }
    }

    float O[16][4];
#pragma unroll
    for (int nf = 0; nf < 16; nf++)
#pragma unroll
        for (int i = 0; i < 4; i++) O[nf][i] = 0.f;
    float m0 = -INFINITY, m1 = -INFINITY, l0 = 0.f, l1 = 0.f;

    // prefetch registers for K and V tiles
    float4 kr[4], vr[4];
    const int fr = tid >> 5, fc4 = (tid & 31) * 4, fw2 = (tid & 31) * 2;

    // ---- prologue: tile 0 into regs, then smem ----
#pragma unroll
    for (int i = 0; i < 4; i++) {
        int r = fr + i * 8;
        kr[i] = *(const float4*)(kg + (size_t)r * (KVH * HD) + fc4);
        vr[i] = *(const float4*)(vg + (size_t)r * (KVH * HD) + fc4);
    }
#pragma unroll
    for (int i = 0; i < 4; i++) {
        int r = fr + i * 8;
        float h0 = bf16_round(kr[i].x), h1 = bf16_round(kr[i].y);
        float h2 = bf16_round(kr[i].z), h3 = bf16_round(kr[i].w);
        *(uint2*)&Kh[r * 68 + fw2] = make_uint2(pack_bf16(h0, h1), pack_bf16(h2, h3));
        *(uint2*)&Kl[r * 68 + fw2] = make_uint2(pack_bf16(kr[i].x - h0, kr[i].y - h1),
                                                pack_bf16(kr[i].z - h2, kr[i].w - h3));
        uint4 vv; vv.x = f2tf32(vr[i].x); vv.y = f2tf32(vr[i].y);
        vv.z = f2tf32(vr[i].z); vv.w = f2tf32(vr[i].w);
        *(uint4*)&Vs[r * 136 + fc4] = vv;
    }
    __syncthreads();

    const int ntiles = (qb + 1) * 4;
    for (int t = 0; t < ntiles; t++) {
        // ---- issue prefetch of tile t+1 ----
        if (t + 1 < ntiles) {
            int tc = (t + 1) * 32;
#pragma unroll
            for (int i = 0; i < 4; i++) {
                int r = tc + fr + i * 8;
                kr[i] = *(const float4*)(kg + (size_t)r * (KVH * HD) + fc4);
                vr[i] = *(const float4*)(vg + (size_t)r * (KVH * HD) + fc4);
            }
        }

        // ---- S = Q @ K^T (split-bf16, 3 MMAs per frag) ----
        float sacc[4][4];
#pragma unroll
        for (int nf = 0; nf < 4; nf++)
#pragma unroll
            for (int i = 0; i < 4; i++) sacc[nf][i] = 0.f;

#pragma unroll
        for (int ks = 0; ks < 8; ks++) {
            int kb = ks * 8;
            int ra0 = (w16 + grp) * 68 + kb + tig;
            int ra1 = (w16 + grp + 8) * 68 + kb + tig;
            uint32_t qh0 = Qh[ra0], qh1 = Qh[ra1], qh2 = Qh[ra0 + 4], qh3 = Qh[ra1 + 4];
            uint32_t ql0 = Ql[ra0], ql1 = Ql[ra1], ql2 = Ql[ra0 + 4], ql3 = Ql[ra1 + 4];
#pragma unroll
            for (int nf = 0; nf < 4; nf++) {
                int rb = (nf * 8 + grp) * 68 + kb + tig;
                uint32_t kh0 = Kh[rb], kh1 = Kh[rb + 4];
                uint32_t kl0 = Kl[rb], kl1 = Kl[rb + 4];
                MMA_BF16(sacc[nf], qh0, qh1, qh2, qh3, kh0, kh1);
                MMA_BF16(sacc[nf], qh0, qh1, qh2, qh3, kl0, kl1);
                MMA_BF16(sacc[nf], ql0, ql1, ql2, ql3, kh0, kh1);
            }
        }

        // ---- causal mask ----
        int tc0 = t * 32;
        if (t >= 4 * qb) {
            int row0 = rbase + w16 + grp, row1 = row0 + 8;
#pragma unroll
            for (int nf = 0; nf < 4; nf++) {
                int col = tc0 + nf * 8 + 2 * tig;
                if (col     > row0) sacc[nf][0] = NEGV;
                if (col + 1 > row0) sacc[nf][1] = NEGV;
                if (col     > row1) sacc[nf][2] = NEGV;
                if (col + 1 > row1) sacc[nf][3] = NEGV;
            }
        }

        // ---- online softmax ----
        float mx0 = -INFINITY, mx1 = -INFINITY;
#pragma unroll
        for (int nf = 0; nf < 4; nf++) {
            mx0 = fmaxf(mx0, fmaxf(sacc[nf][0], sacc[nf][1]));
            mx1 = fmaxf(mx1, fmaxf(sacc[nf][2], sacc[nf][3]));
        }
        mx0 = fmaxf(mx0, __shfl_xor_sync(0xffffffffu, mx0, 1));
        mx0 = fmaxf(mx0, __shfl_xor_sync(0xffffffffu, mx0, 2));
        mx1 = fmaxf(mx1, __shfl_xor_sync(0xffffffffu, mx1, 1));
        mx1 = fmaxf(mx1, __shfl_xor_sync(0xffffffffu, mx1, 2));

        float nm0 = fmaxf(m0, mx0), nm1 = fmaxf(m1, mx1);
        float cr0 = __expf(m0 - nm0), cr1 = __expf(m1 - nm1);
        float s0 = 0.f, s1 = 0.f;
        int pr0 = (w16 + grp) * 36 + 2 * tig;
        int pr1 = (w16 + grp + 8) * 36 + 2 * tig;
#pragma unroll
        for (int nf = 0; nf < 4; nf++) {
            float p0 = __expf(sacc[nf][0] - nm0);
            float p1 = __expf(sacc[nf][1] - nm0);
            float p2 = __expf(sacc[nf][2] - nm1);
            float p3 = __expf(sacc[nf][3] - nm1);
            s0 += p0 + p1; s1 += p2 + p3;
            Ps[pr0 + nf * 8]     = f2tf32(p0);
            Ps[pr0 + nf * 8 + 1] = f2tf32(p1);
            Ps[pr1 + nf * 8]     = f2tf32(p2);
            Ps[pr1 + nf * 8 + 1] = f2tf32(p3);
        }
        s0 += __shfl_xor_sync(0xffffffffu, s0, 1);
        s0 += __shfl_xor_sync(0xffffffffu, s0, 2);
        s1 += __shfl_xor_sync(0xffffffffu, s1, 1);
        s1 += __shfl_xor_sync(0xffffffffu, s1, 2);
        l0 = l0 * cr0 + s0;
        l1 = l1 * cr1 + s1;
        m0 = nm0; m1 = nm1;
#pragma unroll
        for (int nf = 0; nf < 16; nf++) {
            O[nf][0] *= cr0; O[nf][1] *= cr0;
            O[nf][2] *= cr1; O[nf][3] *= cr1;
        }
        __syncwarp();

        // ---- O += P @ V (V native layout [c][d]) ----
#pragma unroll
        for (int ks = 0; ks < 4; ks++) {
            int kb = ks * 8;
            int rp0 = (w16 + grp) * 36 + kb + tig;
            int rp1 = (w16 + grp + 8) * 36 + kb + tig;
            uint32_t pa0 = Ps[rp0], pa1 = Ps[rp1], pa2 = Ps[rp0 + 4], pa3 = Ps[rp1 + 4];
#pragma unroll
            for (int nf = 0; nf < 16; nf++) {
                int n = nf * 8 + grp;
                uint32_t b0 = Vs[(kb + tig) * 136 + n];
                uint32_t b1 = Vs[(kb + tig + 4) * 136 + n];
                MMA_TF32(O[nf], pa0, pa1, pa2, pa3, b0, b1);
            }
        }

        // ---- commit prefetched tile ----
        __syncthreads();
        if (t + 1 < ntiles) {
#pragma unroll
            for (int i = 0; i < 4; i++) {
                int r = fr + i * 8;
                float h0 = bf16_round(kr[i].x), h1 = bf16_round(kr[i].y);
                float h2 = bf16_round(kr[i].z), h3 = bf16_round(kr[i].w);
                *(uint2*)&Kh[r * 68 + fw2] = make_uint2(pack_bf16(h0, h1), pack_bf16(h2, h3));
                *(uint2*)&Kl[r * 68 + fw2] = make_uint2(pack_bf16(kr[i].x - h0, kr[i].y - h1),
                                                        pack_bf16(kr[i].z - h2, kr[i].w - h3));
                uint4 vv; vv.x = f2tf32(vr[i].x); vv.y = f2tf32(vr[i].y);
                vv.z = f2tf32(vr[i].z); vv.w = f2tf32(vr[i].w);
                *(uint4*)&Vs[r * 136 + fc4] = vv;
            }
            __syncthreads();
        }
    }

    // ---- epilogue ----
    float inv0 = 1.f / l0, inv1 = 1.f / l1;
    float* og = o_out + ((size_t)(b * SS) + rbase + w16) * (HH * HD) + h * HD;
#pragma unroll
    for (int nf = 0; nf < 16; nf++) {
        int col = nf * 8 + 2 * tig;
        *(float2*)(og + (size_t)grp * (HH * HD) + col) =
            make_float2(O[nf][0] * inv0, O[nf][1] * inv0);
        *(float2*)(og + (size_t)(grp + 8) * (HH * HD) + col) =
            make_float2(O[nf][2] * inv1, O[nf][3] * inv1);
    }
}

// ---------------- launch ----------------
extern "C" void kernel_launch(void* const* d_in, const int* in_sizes, int n_in,
                              void* d_out, int out_size)
{
    const float* x    = (const float*)d_in[0];
    const float* cosf = (const float*)d_in[1];
    const float* sinf = (const float*)d_in[2];
    const float* ck_in = (const float*)d_in[5];
    const float* cv_in = (const float*)d_in[6];
    const float* wq   = (const float*)d_in[7];
    const float* wk   = (const float*)d_in[8];
    const float* wv   = (const float*)d_in[9];
    const float* wo   = (const float*)d_in[10];

    float* out   = (float*)d_out;
    float* outck = out + (size_t)MM * (HH * HD);
    float* outcv = outck + (size_t)BB * SWW * KVH * HD;

    float* q = nullptr; cudaGetSymbolAddress((void**)&q, g_q);
    float* k = nullptr; cudaGetSymbolAddress((void**)&k, g_k);
    float* v = nullptr; cudaGetSymbolAddress((void**)&v, g_v);
    float* a = nullptr; cudaGetSymbolAddress((void**)&a, g_attn);

    static bool attr_done = false;
    if (!attr_done) {
        cudaFuncSetAttribute(flash_tc_kernel,
                             cudaFuncAttributeMaxDynamicSharedMemorySize, FL_SMEM_BYTES);
        cudaFuncSetAttribute(gemm_tf32_db_kernel,
                             cudaFuncAttributeMaxDynamicSharedMemorySize, G1_SMEM);
        attr_done = true;
    }

    // QKV projections (single-pass tf32, double-buffered)
    gemm_tf32_db_kernel<<<dim3((HH*HD)/128,  MM/128), 256, G1_SMEM>>>(x, wq, q, MM, HH*HD, DD);
    gemm_tf32_db_kernel<<<dim3((KVH*HD)/128, MM/128), 256, G1_SMEM>>>(x, wk, k, MM, KVH*HD, DD);
    gemm_tf32_db_kernel<<<dim3((KVH*HD)/128, MM/128), 256, G1_SMEM>>>(x, wv, v, MM, KVH*HD, DD);

    // RoPE
    {
        int tq = MM * HH * 64;
        rope_kernel<<<(tq + 255) / 256, 256>>>(q, cosf, sinf, HH);
        int tk = MM * KVH * 64;
        rope_kernel<<<(tk + 255) / 256, 256>>>(k, cosf, sinf, KVH);
    }

    // KV cache write-back
    {
        int total = BB * SWW * KVH * HD;
        cache_kernel<<<(total + 255) / 256, 256>>>(k, v, ck_in, cv_in, outck, outcv);
    }

    // tensor-core causal flash attention
    flash_tc_kernel<<<dim3(SS / 128, HH, BB), 256, FL_SMEM_BYTES>>>(q, k, v, a);

    // output projection (single-pass tf32, double-buffered)
    gemm_tf32_db_kernel<<<dim3((HH*HD)/128, MM/128), 256, G1_SMEM>>>(a, wo, out, MM, HH*HD, DD);
}